// round 2
// baseline (speedup 1.0000x reference)
#include <cuda_runtime.h>
#include <cstdint>
#include <cstdio>

// Problem dims (fixed)
#define NROWS 8192
#define VDIM  2048
#define MDIM  128
#define HDIM  512

// Scratch (allocation-free rule: __device__ globals)
__device__ float g_feats [NROWS * MDIM];   // 4 MB
__device__ float g_h     [NROWS * HDIM];   // 16 MB
__device__ float g_feats2[NROWS * MDIM];   // 4 MB

// ---------------- packed fp32 helpers (Blackwell f32x2) ----------------
__device__ __forceinline__ void ffma2(unsigned long long& d,
                                      unsigned long long a,
                                      unsigned long long b) {
    asm volatile("fma.rn.f32x2 %0, %1, %2, %0;" : "+l"(d) : "l"(a), "l"(b));
}
__device__ __forceinline__ float lo32(unsigned long long v) {
    return __uint_as_float((unsigned)(v & 0xffffffffull));
}
__device__ __forceinline__ float hi32(unsigned long long v) {
    return __uint_as_float((unsigned)(v >> 32));
}

// =======================================================================
// Generic 128x64-tile fp32 GEMM:  C[M,N] = epi( A[M,K] @ B )
//   LAY_NT: B is [N,K] row-major (C[m,n] = sum_k A[m,k]*B[n,k])
//   LAY_NN: B is [K,N] row-major (C[m,n] = sum_k A[m,k]*B[k,n])
// EPI_NONE: C = acc
// EPI_SILU: C = silu(acc + bias[n])
// EPI_RES : C = acc + X[m,n]
// 256 threads, per-thread 8 rows x 4 cols via f32x2 (row-paired).
// =======================================================================
#define LAY_NT 0
#define LAY_NN 1
#define EPI_NONE 0
#define EPI_SILU 1
#define EPI_RES  2

template <int LAY, int EPI>
__global__ __launch_bounds__(256)
void gemm_f32(const float* __restrict__ A, const float* __restrict__ B,
              const float* __restrict__ bias, const float* __restrict__ X,
              float* __restrict__ C, int M, int N, int K)
{
    __shared__ float sAt[16 * 128];   // [k][m] transposed
    __shared__ float sBd[16 * 132];   // [k][2*c] duplicated pairs (+pad)

    const int tid = threadIdx.x;
    const int tr  = tid >> 4;    // 0..15 -> rows 8*tr..8*tr+7
    const int ti  = tid & 15;    // 0..15 -> cols 4*ti..4*ti+3
    const int m0  = blockIdx.x * 128;
    const int n0  = blockIdx.y * 64;

    unsigned long long acc[4][4];
#pragma unroll
    for (int i = 0; i < 4; i++)
#pragma unroll
        for (int j = 0; j < 4; j++) acc[i][j] = 0ull;

    const int arow = tid & 127;     // A loader row
    const int af   = tid >> 7;      // 0/1 -> k-slots {0,8} / {4,12}

    for (int kb = 0; kb < K; kb += 16) {
        // ---- global loads (issued before barrier) ----
        const float* ap = A + (size_t)(m0 + arow) * K + kb + af * 4;
        float4 va0 = *(const float4*)(ap);
        float4 va1 = *(const float4*)(ap + 8);

        float4 vb;
        int bk, bc;
        if (LAY == LAY_NT) {
            bc = tid >> 2;            // 0..63 column
            bk = (tid & 3) * 4;       // k slot
            vb = *(const float4*)(B + (size_t)(n0 + bc) * K + kb + bk);
        } else {
            bk = tid >> 4;            // 0..15 k row
            bc = (tid & 15) * 4;      // column group
            vb = *(const float4*)(B + (size_t)(kb + bk) * N + n0 + bc);
        }

        __syncthreads();   // previous chunk fully consumed

        // ---- stage A transposed ----
        {
            int k0 = af * 4;
            sAt[(k0 + 0) * 128 + arow] = va0.x;
            sAt[(k0 + 1) * 128 + arow] = va0.y;
            sAt[(k0 + 2) * 128 + arow] = va0.z;
            sAt[(k0 + 3) * 128 + arow] = va0.w;
            sAt[(k0 + 8) * 128 + arow] = va1.x;
            sAt[(k0 + 9) * 128 + arow] = va1.y;
            sAt[(k0 +10) * 128 + arow] = va1.z;
            sAt[(k0 +11) * 128 + arow] = va1.w;
        }
        // ---- stage B duplicated ----
        if (LAY == LAY_NT) {
            *(float2*)&sBd[(bk + 0) * 132 + 2 * bc] = make_float2(vb.x, vb.x);
            *(float2*)&sBd[(bk + 1) * 132 + 2 * bc] = make_float2(vb.y, vb.y);
            *(float2*)&sBd[(bk + 2) * 132 + 2 * bc] = make_float2(vb.z, vb.z);
            *(float2*)&sBd[(bk + 3) * 132 + 2 * bc] = make_float2(vb.w, vb.w);
        } else {
            *(float2*)&sBd[bk * 132 + 2 * (bc + 0)] = make_float2(vb.x, vb.x);
            *(float2*)&sBd[bk * 132 + 2 * (bc + 1)] = make_float2(vb.y, vb.y);
            *(float2*)&sBd[bk * 132 + 2 * (bc + 2)] = make_float2(vb.z, vb.z);
            *(float2*)&sBd[bk * 132 + 2 * (bc + 3)] = make_float2(vb.w, vb.w);
        }
        __syncthreads();

        // ---- compute 16 k-steps ----
#pragma unroll
        for (int k = 0; k < 16; k++) {
            const float* br = sBd + k * 132;
            const float* ar = sAt + k * 128;
            ulonglong2 b01 = *(const ulonglong2*)(br + 8 * ti);
            ulonglong2 b23 = *(const ulonglong2*)(br + 8 * ti + 4);
            ulonglong2 a01 = *(const ulonglong2*)(ar + 8 * tr);
            ulonglong2 a23 = *(const ulonglong2*)(ar + 8 * tr + 4);
            ffma2(acc[0][0], a01.x, b01.x); ffma2(acc[0][1], a01.x, b01.y);
            ffma2(acc[0][2], a01.x, b23.x); ffma2(acc[0][3], a01.x, b23.y);
            ffma2(acc[1][0], a01.y, b01.x); ffma2(acc[1][1], a01.y, b01.y);
            ffma2(acc[1][2], a01.y, b23.x); ffma2(acc[1][3], a01.y, b23.y);
            ffma2(acc[2][0], a23.x, b01.x); ffma2(acc[2][1], a23.x, b01.y);
            ffma2(acc[2][2], a23.x, b23.x); ffma2(acc[2][3], a23.x, b23.y);
            ffma2(acc[3][0], a23.y, b01.x); ffma2(acc[3][1], a23.y, b01.y);
            ffma2(acc[3][2], a23.y, b23.x); ffma2(acc[3][3], a23.y, b23.y);
        }
    }

    // ---- epilogue ----
    float4 bv = make_float4(0.f, 0.f, 0.f, 0.f);
    if (EPI == EPI_SILU) bv = *(const float4*)(bias + n0 + 4 * ti);

#pragma unroll
    for (int rp = 0; rp < 4; rp++) {
#pragma unroll
        for (int hh = 0; hh < 2; hh++) {
            int r = 8 * tr + 2 * rp + hh;
            float v0 = hh ? hi32(acc[rp][0]) : lo32(acc[rp][0]);
            float v1 = hh ? hi32(acc[rp][1]) : lo32(acc[rp][1]);
            float v2 = hh ? hi32(acc[rp][2]) : lo32(acc[rp][2]);
            float v3 = hh ? hi32(acc[rp][3]) : lo32(acc[rp][3]);
            size_t base = (size_t)(m0 + r) * N + n0 + 4 * ti;
            float4 outv;
            if (EPI == EPI_SILU) {
                float z0 = v0 + bv.x, z1 = v1 + bv.y, z2 = v2 + bv.z, z3 = v3 + bv.w;
                outv.x = z0 / (1.f + expf(-z0));
                outv.y = z1 / (1.f + expf(-z1));
                outv.z = z2 / (1.f + expf(-z2));
                outv.w = z3 / (1.f + expf(-z3));
            } else if (EPI == EPI_RES) {
                float4 xv = *(const float4*)(X + base);
                outv = make_float4(v0 + xv.x, v1 + xv.y, v2 + xv.z, v3 + xv.w);
            } else {
                outv = make_float4(v0, v1, v2, v3);
            }
            *(float4*)(C + base) = outv;
        }
    }
}

// =======================================================================
// K3: the bilinear core.
//   feats2[n,i] += sum_{j,k} W2[(i*128+j)*512 + k] * feats[n,j] * h[n,k]
// Formulated as GEMM with implicit operand Q[n,(j,k)] = feats[n,j]*h[n,k].
// CTA: 64 rows x all 128 i. 2048 chunks of (1 j, 32 k). Double-buffered.
// Thread tile: 4 rows x 8 i, via 16 FFMA2 per k-step.
// =======================================================================
#define K3_SMEM_FLOATS (8192 + 32768 + 2*4096 + 2*4224)   // 57600 -> 230400 B

__global__ __launch_bounds__(256, 1)
void k3_kernel(const float* __restrict__ W2,
               const float* __restrict__ feats,
               const float* __restrict__ h,
               float* __restrict__ feats2)
{
    extern __shared__ float sm[];
    float* sF = sm;                    // [64][128]
    float* sH = sm + 8192;             // [64][512]
    float* sA = sm + 8192 + 32768;     // 2 x [32][128]   (W2 chunk, [k'][i])
    float* sQ = sA + 2 * 4096;         // 2 x [32][132]   (dup q pairs, [k'][2r])

    const int tid = threadIdx.x;
    const int tr  = tid >> 4;          // 0..15 -> rows 4*tr..4*tr+3
    const int ti  = tid & 15;          // 0..15 -> i in {4ti..4ti+3, 4ti+64..4ti+67}
    const int n0  = blockIdx.x * 64;

    // ---- load feats / h tiles (contiguous blocks) ----
    {
        const float4* s1 = (const float4*)(feats + (size_t)n0 * 128);
        float4*       d1 = (float4*)sF;
        for (int i = tid; i < 2048; i += 256) d1[i] = s1[i];
        const float4* s2 = (const float4*)(h + (size_t)n0 * 512);
        float4*       d2 = (float4*)sH;
        for (int i = tid; i < 8192; i += 256) d2[i] = s2[i];
    }

    unsigned long long acc[4][4];
#pragma unroll
    for (int i = 0; i < 4; i++)
#pragma unroll
        for (int j = 0; j < 4; j++) acc[i][j] = 0ull;

    const int ai = tid >> 1;           // A-loader: i row 0..127
    const int ah = tid & 1;            // k half: 0..15 / 16..31
    const int qk = tid & 31;           // Q-builder: k' 0..31
    const int qr = (tid >> 5) * 8;     // rows qr..qr+7

    float4 pf0, pf1, pf2, pf3;

    // prefetch chunk 0 (j=0, k0=0)
    {
        const float* gp = W2 + ((size_t)ai * 128 + 0) * 512 + 0 + ah * 16;
        pf0 = *(const float4*)(gp);
        pf1 = *(const float4*)(gp + 4);
        pf2 = *(const float4*)(gp + 8);
        pf3 = *(const float4*)(gp + 12);
    }
    __syncthreads();   // sF/sH ready

    // stage chunk 0 into buffer 0
    {
        int k0 = ah * 16;
        sA[(k0 + 0) * 128 + ai] = pf0.x;  sA[(k0 + 1) * 128 + ai] = pf0.y;
        sA[(k0 + 2) * 128 + ai] = pf0.z;  sA[(k0 + 3) * 128 + ai] = pf0.w;
        sA[(k0 + 4) * 128 + ai] = pf1.x;  sA[(k0 + 5) * 128 + ai] = pf1.y;
        sA[(k0 + 6) * 128 + ai] = pf1.z;  sA[(k0 + 7) * 128 + ai] = pf1.w;
        sA[(k0 + 8) * 128 + ai] = pf2.x;  sA[(k0 + 9) * 128 + ai] = pf2.y;
        sA[(k0 +10) * 128 + ai] = pf2.z;  sA[(k0 +11) * 128 + ai] = pf2.w;
        sA[(k0 +12) * 128 + ai] = pf3.x;  sA[(k0 +13) * 128 + ai] = pf3.y;
        sA[(k0 +14) * 128 + ai] = pf3.z;  sA[(k0 +15) * 128 + ai] = pf3.w;
#pragma unroll
        for (int rr = 0; rr < 8; rr++) {
            int r = qr + rr;
            float q = sF[r * 128 + 0] * sH[r * 512 + 0 + qk];
            *(float2*)(sQ + qk * 132 + 2 * r) = make_float2(q, q);
        }
    }
    __syncthreads();

    for (int c = 0; c < 2048; ++c) {
        const int b  = c & 1;
        const int cn = c + 1;
        const int jn = cn >> 4;
        const int kn = (cn & 15) << 5;

        if (cn < 2048) {   // prefetch next chunk (hidden under compute)
            const float* gp = W2 + ((size_t)ai * 128 + jn) * 512 + kn + ah * 16;
            pf0 = *(const float4*)(gp);
            pf1 = *(const float4*)(gp + 4);
            pf2 = *(const float4*)(gp + 8);
            pf3 = *(const float4*)(gp + 12);
        }

        const float* ab = sA + b * 4096;
        const float* qb = sQ + b * 4224;
#pragma unroll
        for (int k = 0; k < 32; k++) {
            const float* qr_ = qb + k * 132 + 8 * tr;
            const float* ar_ = ab + k * 128 + 4 * ti;
            ulonglong2 q01 = *(const ulonglong2*)(qr_);
            ulonglong2 q23 = *(const ulonglong2*)(qr_ + 4);
            ulonglong2 a01 = *(const ulonglong2*)(ar_);
            ulonglong2 a23 = *(const ulonglong2*)(ar_ + 64);
            ffma2(acc[0][0], q01.x, a01.x); ffma2(acc[0][1], q01.x, a01.y);
            ffma2(acc[0][2], q01.x, a23.x); ffma2(acc[0][3], q01.x, a23.y);
            ffma2(acc[1][0], q01.y, a01.x); ffma2(acc[1][1], q01.y, a01.y);
            ffma2(acc[1][2], q01.y, a23.x); ffma2(acc[1][3], q01.y, a23.y);
            ffma2(acc[2][0], q23.x, a01.x); ffma2(acc[2][1], q23.x, a01.y);
            ffma2(acc[2][2], q23.x, a23.x); ffma2(acc[2][3], q23.x, a23.y);
            ffma2(acc[3][0], q23.y, a01.x); ffma2(acc[3][1], q23.y, a01.y);
            ffma2(acc[3][2], q23.y, a23.x); ffma2(acc[3][3], q23.y, a23.y);
        }
        __syncthreads();

        if (cn < 2048) {   // stage next chunk into other buffer
            float* an = sA + (b ^ 1) * 4096;
            int k0 = ah * 16;
            an[(k0 + 0) * 128 + ai] = pf0.x;  an[(k0 + 1) * 128 + ai] = pf0.y;
            an[(k0 + 2) * 128 + ai] = pf0.z;  an[(k0 + 3) * 128 + ai] = pf0.w;
            an[(k0 + 4) * 128 + ai] = pf1.x;  an[(k0 + 5) * 128 + ai] = pf1.y;
            an[(k0 + 6) * 128 + ai] = pf1.z;  an[(k0 + 7) * 128 + ai] = pf1.w;
            an[(k0 + 8) * 128 + ai] = pf2.x;  an[(k0 + 9) * 128 + ai] = pf2.y;
            an[(k0 +10) * 128 + ai] = pf2.z;  an[(k0 +11) * 128 + ai] = pf2.w;
            an[(k0 +12) * 128 + ai] = pf3.x;  an[(k0 +13) * 128 + ai] = pf3.y;
            an[(k0 +14) * 128 + ai] = pf3.z;  an[(k0 +15) * 128 + ai] = pf3.w;
            float* qn = sQ + (b ^ 1) * 4224;
#pragma unroll
            for (int rr = 0; rr < 8; rr++) {
                int r = qr + rr;
                float q = sF[r * 128 + jn] * sH[r * 512 + kn + qk];
                *(float2*)(qn + qk * 132 + 2 * r) = make_float2(q, q);
            }
        }
        __syncthreads();
    }

    // ---- epilogue: accumulate onto bias term already in feats2 ----
#pragma unroll
    for (int r = 0; r < 4; r++) {
        size_t base = (size_t)(n0 + 4 * tr + r) * 128;
#pragma unroll
        for (int p = 0; p < 4; p++) {
            int col = (p < 2) ? (4 * ti + 2 * p) : (4 * ti + 64 + 2 * (p - 2));
            float2 prev = *(float2*)(feats2 + base + col);
            prev.x += lo32(acc[r][p]);
            prev.y += hi32(acc[r][p]);
            *(float2*)(feats2 + base + col) = prev;
        }
    }
}

// =======================================================================
// Host launcher
// =======================================================================
extern "C" void kernel_launch(void* const* d_in, const int* in_sizes, int n_in,
                              void* d_out, int out_size)
{
    const float* x    = (const float*)d_in[0];
    const float* Wmap = (const float*)d_in[1];
    const float* W1   = (const float*)d_in[2];
    const float* b1   = (const float*)d_in[3];
    const float* W2   = (const float*)d_in[4];
    const float* b2   = (const float*)d_in[5];
    float* out = (float*)d_out;

    void *pf, *ph, *pf2;
    cudaGetSymbolAddress(&pf,  g_feats);
    cudaGetSymbolAddress(&ph,  g_h);
    cudaGetSymbolAddress(&pf2, g_feats2);
    float* feats  = (float*)pf;
    float* hbuf   = (float*)ph;
    float* feats2 = (float*)pf2;

    cudaFuncSetAttribute(k3_kernel, cudaFuncAttributeMaxDynamicSharedMemorySize,
                         K3_SMEM_FLOATS * 4);

    dim3 blk(256);

    // 1) feats = x @ W_map^T          (M=8192, N=128, K=2048, NT)
    gemm_f32<LAY_NT, EPI_NONE><<<dim3(NROWS / 128, MDIM / 64), blk>>>(
        x, Wmap, nullptr, nullptr, feats, NROWS, MDIM, VDIM);

    // 2) h = silu(feats @ W1^T + b1)  (M=8192, N=512, K=128, NT)
    gemm_f32<LAY_NT, EPI_SILU><<<dim3(NROWS / 128, HDIM / 64), blk>>>(
        feats, W1, b1, nullptr, hbuf, NROWS, HDIM, MDIM);

    // 3) feats2 = feats @ B2^T  (bias term of A; also zero-inits feats2)
    //    B2[i][j] = b2[i*128+j]  -> NT with B=b2, K=128
    gemm_f32<LAY_NT, EPI_NONE><<<dim3(NROWS / 128, MDIM / 64), blk>>>(
        feats, b2, nullptr, nullptr, feats2, NROWS, MDIM, MDIM);

    // 4) feats2 += implicit-Q GEMM against W2   (the 137 GF core)
    k3_kernel<<<NROWS / 64, blk, K3_SMEM_FLOATS * 4>>>(W2, feats, hbuf, feats2);

    // 5) out = x + feats2 @ W_map     (M=8192, N=2048, K=128, NN)
    gemm_f32<LAY_NN, EPI_RES><<<dim3(NROWS / 128, VDIM / 64), blk>>>(
        feats2, Wmap, nullptr, x, out, NROWS, VDIM, MDIM);
}

// round 4
// speedup vs baseline: 3.4183x; 3.4183x over previous
#include <cuda_runtime.h>
#include <cstdint>
#include <cstdio>

// Problem dims (fixed)
#define NROWS 8192
#define VDIM  2048
#define MDIM  128
#define HDIM  512

// Scratch (allocation-free rule: __device__ globals)
__device__ __align__(256) float g_feats [NROWS * MDIM];   // 4 MB
__device__ __align__(256) float g_h     [NROWS * HDIM];   // 16 MB
__device__ __align__(256) float g_feats2[NROWS * MDIM];   // 4 MB

// ---------------- packed fp32 helpers (Blackwell f32x2) ----------------
__device__ __forceinline__ void ffma2(unsigned long long& d,
                                      unsigned long long a,
                                      unsigned long long b) {
    asm volatile("fma.rn.f32x2 %0, %1, %2, %0;" : "+l"(d) : "l"(a), "l"(b));
}
__device__ __forceinline__ float lo32(unsigned long long v) {
    return __uint_as_float((unsigned)(v & 0xffffffffull));
}
__device__ __forceinline__ float hi32(unsigned long long v) {
    return __uint_as_float((unsigned)(v >> 32));
}

// =======================================================================
// Generic 128x64-tile fp32 GEMM (steps 1,2,3,5) — unchanged
// =======================================================================
#define LAY_NT 0
#define LAY_NN 1
#define EPI_NONE 0
#define EPI_SILU 1
#define EPI_RES  2

template <int LAY, int EPI>
__global__ __launch_bounds__(256)
void gemm_f32(const float* __restrict__ A, const float* __restrict__ B,
              const float* __restrict__ bias, const float* __restrict__ X,
              float* __restrict__ C, int M, int N, int K)
{
    __shared__ float sAt[16 * 128];
    __shared__ float sBd[16 * 132];

    const int tid = threadIdx.x;
    const int tr  = tid >> 4;
    const int ti  = tid & 15;
    const int m0  = blockIdx.x * 128;
    const int n0  = blockIdx.y * 64;

    unsigned long long acc[4][4];
#pragma unroll
    for (int i = 0; i < 4; i++)
#pragma unroll
        for (int j = 0; j < 4; j++) acc[i][j] = 0ull;

    const int arow = tid & 127;
    const int af   = tid >> 7;

    for (int kb = 0; kb < K; kb += 16) {
        const float* ap = A + (size_t)(m0 + arow) * K + kb + af * 4;
        float4 va0 = *(const float4*)(ap);
        float4 va1 = *(const float4*)(ap + 8);

        float4 vb;
        int bk, bc;
        if (LAY == LAY_NT) {
            bc = tid >> 2;
            bk = (tid & 3) * 4;
            vb = *(const float4*)(B + (size_t)(n0 + bc) * K + kb + bk);
        } else {
            bk = tid >> 4;
            bc = (tid & 15) * 4;
            vb = *(const float4*)(B + (size_t)(kb + bk) * N + n0 + bc);
        }

        __syncthreads();

        {
            int k0 = af * 4;
            sAt[(k0 + 0) * 128 + arow] = va0.x;
            sAt[(k0 + 1) * 128 + arow] = va0.y;
            sAt[(k0 + 2) * 128 + arow] = va0.z;
            sAt[(k0 + 3) * 128 + arow] = va0.w;
            sAt[(k0 + 8) * 128 + arow] = va1.x;
            sAt[(k0 + 9) * 128 + arow] = va1.y;
            sAt[(k0 +10) * 128 + arow] = va1.z;
            sAt[(k0 +11) * 128 + arow] = va1.w;
        }
        if (LAY == LAY_NT) {
            *(float2*)&sBd[(bk + 0) * 132 + 2 * bc] = make_float2(vb.x, vb.x);
            *(float2*)&sBd[(bk + 1) * 132 + 2 * bc] = make_float2(vb.y, vb.y);
            *(float2*)&sBd[(bk + 2) * 132 + 2 * bc] = make_float2(vb.z, vb.z);
            *(float2*)&sBd[(bk + 3) * 132 + 2 * bc] = make_float2(vb.w, vb.w);
        } else {
            *(float2*)&sBd[bk * 132 + 2 * (bc + 0)] = make_float2(vb.x, vb.x);
            *(float2*)&sBd[bk * 132 + 2 * (bc + 1)] = make_float2(vb.y, vb.y);
            *(float2*)&sBd[bk * 132 + 2 * (bc + 2)] = make_float2(vb.z, vb.z);
            *(float2*)&sBd[bk * 132 + 2 * (bc + 3)] = make_float2(vb.w, vb.w);
        }
        __syncthreads();

#pragma unroll
        for (int k = 0; k < 16; k++) {
            const float* br = sBd + k * 132;
            const float* ar = sAt + k * 128;
            ulonglong2 b01 = *(const ulonglong2*)(br + 8 * ti);
            ulonglong2 b23 = *(const ulonglong2*)(br + 8 * ti + 4);
            ulonglong2 a01 = *(const ulonglong2*)(ar + 8 * tr);
            ulonglong2 a23 = *(const ulonglong2*)(ar + 8 * tr + 4);
            ffma2(acc[0][0], a01.x, b01.x); ffma2(acc[0][1], a01.x, b01.y);
            ffma2(acc[0][2], a01.x, b23.x); ffma2(acc[0][3], a01.x, b23.y);
            ffma2(acc[1][0], a01.y, b01.x); ffma2(acc[1][1], a01.y, b01.y);
            ffma2(acc[1][2], a01.y, b23.x); ffma2(acc[1][3], a01.y, b23.y);
            ffma2(acc[2][0], a23.x, b01.x); ffma2(acc[2][1], a23.x, b01.y);
            ffma2(acc[2][2], a23.x, b23.x); ffma2(acc[2][3], a23.x, b23.y);
            ffma2(acc[3][0], a23.y, b01.x); ffma2(acc[3][1], a23.y, b01.y);
            ffma2(acc[3][2], a23.y, b23.x); ffma2(acc[3][3], a23.y, b23.y);
        }
    }

    float4 bv = make_float4(0.f, 0.f, 0.f, 0.f);
    if (EPI == EPI_SILU) bv = *(const float4*)(bias + n0 + 4 * ti);

#pragma unroll
    for (int rp = 0; rp < 4; rp++) {
#pragma unroll
        for (int hh = 0; hh < 2; hh++) {
            int r = 8 * tr + 2 * rp + hh;
            float v0 = hh ? hi32(acc[rp][0]) : lo32(acc[rp][0]);
            float v1 = hh ? hi32(acc[rp][1]) : lo32(acc[rp][1]);
            float v2 = hh ? hi32(acc[rp][2]) : lo32(acc[rp][2]);
            float v3 = hh ? hi32(acc[rp][3]) : lo32(acc[rp][3]);
            size_t base = (size_t)(m0 + r) * N + n0 + 4 * ti;
            float4 outv;
            if (EPI == EPI_SILU) {
                float z0 = v0 + bv.x, z1 = v1 + bv.y, z2 = v2 + bv.z, z3 = v3 + bv.w;
                outv.x = z0 / (1.f + expf(-z0));
                outv.y = z1 / (1.f + expf(-z1));
                outv.z = z2 / (1.f + expf(-z2));
                outv.w = z3 / (1.f + expf(-z3));
            } else if (EPI == EPI_RES) {
                float4 xv = *(const float4*)(X + base);
                outv = make_float4(v0 + xv.x, v1 + xv.y, v2 + xv.z, v3 + xv.w);
            } else {
                outv = make_float4(v0, v1, v2, v3);
            }
            *(float4*)(C + base) = outv;
        }
    }
}

// =======================================================================
// K3 via legacy mma.sync (tf32, sm_80+ PTX — family-generic target safe):
//   C1[n, i*128+j] = sum_k h[n,k] * W2[(i*128+j), k]     (NT GEMM, K=512)
//   feats2[n,i]   += sum_j C1[n, i*128+j] * feats[n,j]   (epilogue)
// CTA tile: 128(M) x 256(N), K chunks of 32, double-buffered cp.async.
// 8 warps in 2x4 grid; warp tile 64x64 via m16n8k8 (4 mt x 8 nt).
// Smem stride 36 floats -> fragment LDS bank == lane id (conflict-free).
// =======================================================================
#define K3_BM   128
#define K3_BN   256
#define K3_KC   32
#define K3_NCH  16
#define K3_ASTR 36
#define K3_ASTG (K3_BM * K3_ASTR)          // 4608 floats
#define K3_BSTG (K3_BN * K3_ASTR)          // 9216 floats
#define K3_SMEM_BYTES (2 * (K3_ASTG + K3_BSTG) * 4 + 2048 + 256)

__device__ __forceinline__ uint32_t smem_u32(const void* p) {
    uint32_t a;
    asm("{ .reg .u64 t; cvta.to.shared.u64 t, %1; cvt.u32.u64 %0, t; }"
        : "=r"(a) : "l"(p));
    return a;
}
__device__ __forceinline__ void cp_async16(uint32_t dst, const void* src) {
    asm volatile("cp.async.cg.shared.global [%0], [%1], 16;"
                 :: "r"(dst), "l"(src));
}
__device__ __forceinline__ void cp_commit() {
    asm volatile("cp.async.commit_group;" ::: "memory");
}
template <int N>
__device__ __forceinline__ void cp_wait() {
    asm volatile("cp.async.wait_group %0;" :: "n"(N) : "memory");
}
__device__ __forceinline__ uint32_t f2tf32(float f) {
    uint32_t r;
    asm("cvt.rna.tf32.f32 %0, %1;" : "=r"(r) : "f"(f));
    return r;
}
__device__ __forceinline__ void mma_tf32(float* d, const uint32_t* a,
                                         const uint32_t* b) {
    asm volatile(
        "mma.sync.aligned.m16n8k8.row.col.f32.tf32.tf32.f32 "
        "{%0,%1,%2,%3}, {%4,%5,%6,%7}, {%8,%9}, {%0,%1,%2,%3};"
        : "+f"(d[0]), "+f"(d[1]), "+f"(d[2]), "+f"(d[3])
        : "r"(a[0]), "r"(a[1]), "r"(a[2]), "r"(a[3]), "r"(b[0]), "r"(b[1]));
}

__global__ __launch_bounds__(256, 1)
void k3_mma(const float* __restrict__ W2,
            const float* __restrict__ feats,
            const float* __restrict__ h,
            float* __restrict__ feats2)
{
    extern __shared__ char smem[];
    float* sAf = (float*)smem;                                  // [2][4608]
    float* sBf = (float*)(smem + 2 * K3_ASTG * 4);              // [2][9216]
    float* sRed = (float*)(smem + 2 * (K3_ASTG + K3_BSTG) * 4); // [128][4]
    const uint32_t sA_u = smem_u32(sAf);
    const uint32_t sB_u = smem_u32(sBf);

    const int tid  = threadIdx.x;
    const int wid  = tid >> 5;
    const int lane = tid & 31;
    const int wr   = wid >> 2;         // 0..1 -> rows 64*wr
    const int wc   = wid & 3;          // 0..3 -> cols 64*wc
    const int qr   = lane >> 2;        // 0..7
    const int qc   = lane & 3;         // 0..3
    const int m0   = blockIdx.x * K3_BM;
    const int nb   = blockIdx.y;       // N-block: cols [nb*256, nb*256+256)

    float acc[4][8][4];
#pragma unroll
    for (int mt = 0; mt < 4; mt++)
#pragma unroll
        for (int nt = 0; nt < 8; nt++)
#pragma unroll
            for (int v = 0; v < 4; v++) acc[mt][nt][v] = 0.f;

    // chunk loader: A = h rows [m0,m0+128), B = W2 rows [nb*256, +256), KC cols
    auto load_chunk = [&](int c) {
        const int s = c & 1;
        const int kc = c * K3_KC;
        const uint32_t ab = sA_u + s * K3_ASTG * 4;
        const uint32_t bb = sB_u + s * K3_BSTG * 4;
#pragma unroll
        for (int o = 0; o < 4; o++) {                 // 128 rows * 8 groups
            int li = o * 256 + tid;
            int row = li >> 3, g = li & 7;
            cp_async16(ab + (row * K3_ASTR + g * 4) * 4,
                       h + (size_t)(m0 + row) * HDIM + kc + g * 4);
        }
#pragma unroll
        for (int o = 0; o < 8; o++) {                 // 256 rows * 8 groups
            int li = o * 256 + tid;
            int row = li >> 3, g = li & 7;
            cp_async16(bb + (row * K3_ASTR + g * 4) * 4,
                       W2 + (size_t)(nb * K3_BN + row) * HDIM + kc + g * 4);
        }
        cp_commit();
    };

    load_chunk(0);

    for (int c = 0; c < K3_NCH; c++) {
        if (c + 1 < K3_NCH) { load_chunk(c + 1); cp_wait<1>(); }
        else                { cp_wait<0>(); }
        __syncthreads();

        const float* A = sAf + (c & 1) * K3_ASTG;
        const float* B = sBf + (c & 1) * K3_BSTG;

#pragma unroll
        for (int k8 = 0; k8 < 4; k8++) {
            const int k0 = k8 * 8;
            uint32_t af[4][4], bf[8][2];
#pragma unroll
            for (int mt = 0; mt < 4; mt++) {
                const float* ar = A + (wr * 64 + mt * 16 + qr) * K3_ASTR + k0 + qc;
                af[mt][0] = f2tf32(ar[0]);
                af[mt][1] = f2tf32(ar[8 * K3_ASTR]);
                af[mt][2] = f2tf32(ar[4]);
                af[mt][3] = f2tf32(ar[8 * K3_ASTR + 4]);
            }
#pragma unroll
            for (int nt = 0; nt < 8; nt++) {
                const float* br = B + (wc * 64 + nt * 8 + qr) * K3_ASTR + k0 + qc;
                bf[nt][0] = f2tf32(br[0]);
                bf[nt][1] = f2tf32(br[4]);
            }
#pragma unroll
            for (int mt = 0; mt < 4; mt++)
#pragma unroll
                for (int nt = 0; nt < 8; nt++)
                    mma_tf32(acc[mt][nt], af[mt], bf[nt]);
        }
        __syncthreads();
    }

    // ---- epilogue: stage feats [128 rows][128 j] (stride 132), reduce ----
    float* fs = sAf;   // reuse pipeline smem (67584 B needed, 110592 free)
#pragma unroll
    for (int o = 0; o < 16; o++) {
        int li = o * 256 + tid;        // 4096 float4 tasks
        int row = li >> 5, g = li & 31;
        float4 v = *(const float4*)(feats + (size_t)(m0 + row) * MDIM + g * 4);
        float* d = fs + row * 132 + g * 4;
        d[0] = v.x; d[1] = v.y; d[2] = v.z; d[3] = v.w;
    }
    __syncthreads();

#pragma unroll
    for (int mt = 0; mt < 4; mt++) {
#pragma unroll
        for (int h2 = 0; h2 < 2; h2++) {
            int rl = wr * 64 + mt * 16 + qr + 8 * h2;
            float p = 0.f;
#pragma unroll
            for (int nt = 0; nt < 8; nt++) {
                int j0 = (wc & 1) * 64 + nt * 8 + 2 * qc;
                p = fmaf(acc[mt][nt][2 * h2],     fs[rl * 132 + j0],     p);
                p = fmaf(acc[mt][nt][2 * h2 + 1], fs[rl * 132 + j0 + 1], p);
            }
            p += __shfl_xor_sync(0xffffffffu, p, 1);
            p += __shfl_xor_sync(0xffffffffu, p, 2);
            if (qc == 0) sRed[rl * 4 + wc] = p;
        }
    }
    __syncthreads();

    {
        int row = tid >> 1, iv = tid & 1;
        float s = sRed[row * 4 + iv * 2] + sRed[row * 4 + iv * 2 + 1];
        size_t o = (size_t)(m0 + row) * MDIM + nb * 2 + iv;
        feats2[o] += s;      // exclusive (row, i) per CTA
    }
}

// =======================================================================
// Host launcher
// =======================================================================
extern "C" void kernel_launch(void* const* d_in, const int* in_sizes, int n_in,
                              void* d_out, int out_size)
{
    const float* x    = (const float*)d_in[0];
    const float* Wmap = (const float*)d_in[1];
    const float* W1   = (const float*)d_in[2];
    const float* b1   = (const float*)d_in[3];
    const float* W2   = (const float*)d_in[4];
    const float* b2   = (const float*)d_in[5];
    float* out = (float*)d_out;

    void *pf, *ph, *pf2;
    cudaGetSymbolAddress(&pf,  g_feats);
    cudaGetSymbolAddress(&ph,  g_h);
    cudaGetSymbolAddress(&pf2, g_feats2);
    float* feats  = (float*)pf;
    float* hbuf   = (float*)ph;
    float* feats2 = (float*)pf2;

    cudaFuncSetAttribute(k3_mma, cudaFuncAttributeMaxDynamicSharedMemorySize,
                         K3_SMEM_BYTES);

    dim3 blk(256);

    // 1) feats = x @ W_map^T          (M=8192, N=128, K=2048, NT)
    gemm_f32<LAY_NT, EPI_NONE><<<dim3(NROWS / 128, MDIM / 64), blk>>>(
        x, Wmap, nullptr, nullptr, feats, NROWS, MDIM, VDIM);

    // 2) h = silu(feats @ W1^T + b1)  (M=8192, N=512, K=128, NT)
    gemm_f32<LAY_NT, EPI_SILU><<<dim3(NROWS / 128, HDIM / 64), blk>>>(
        feats, W1, b1, nullptr, hbuf, NROWS, HDIM, MDIM);

    // 3) feats2 = feats @ B2^T  (bias term of A; zero-inits feats2)
    gemm_f32<LAY_NT, EPI_NONE><<<dim3(NROWS / 128, MDIM / 64), blk>>>(
        feats, b2, nullptr, nullptr, feats2, NROWS, MDIM, MDIM);

    // 4) feats2 += epilogue-reduced (h @ W2^T) . feats   — tf32 mma.sync
    k3_mma<<<dim3(NROWS / K3_BM, 16384 / K3_BN), blk, K3_SMEM_BYTES>>>(
        W2, feats, hbuf, feats2);

    // 5) out = x + feats2 @ W_map     (M=8192, N=2048, K=128, NN)
    gemm_f32<LAY_NN, EPI_RES><<<dim3(NROWS / 128, VDIM / 64), blk>>>(
        feats2, Wmap, nullptr, x, out, NROWS, VDIM, MDIM);
}

// round 5
// speedup vs baseline: 3.8190x; 1.1172x over previous
#include <cuda_runtime.h>
#include <cstdint>
#include <cstdio>

// Problem dims (fixed)
#define NROWS 8192
#define VDIM  2048
#define MDIM  128
#define HDIM  512

// Scratch (allocation-free rule: __device__ globals)
__device__ __align__(256) float g_feats [NROWS * MDIM];   // 4 MB
__device__ __align__(256) float g_h     [NROWS * HDIM];   // 16 MB
__device__ __align__(256) float g_feats2[NROWS * MDIM];   // 4 MB
__device__ __align__(256) float g_wmapT [VDIM * MDIM];    // 1 MB

// ---------------- packed fp32 helpers ----------------
__device__ __forceinline__ void ffma2(unsigned long long& d,
                                      unsigned long long a,
                                      unsigned long long b) {
    asm volatile("fma.rn.f32x2 %0, %1, %2, %0;" : "+l"(d) : "l"(a), "l"(b));
}
__device__ __forceinline__ float lo32(unsigned long long v) {
    return __uint_as_float((unsigned)(v & 0xffffffffull));
}
__device__ __forceinline__ float hi32(unsigned long long v) {
    return __uint_as_float((unsigned)(v >> 32));
}

// ---------------- common PTX helpers ----------------
__device__ __forceinline__ uint32_t smem_u32(const void* p) {
    uint32_t a;
    asm("{ .reg .u64 t; cvta.to.shared.u64 t, %1; cvt.u32.u64 %0, t; }"
        : "=r"(a) : "l"(p));
    return a;
}
__device__ __forceinline__ void cp_async16(uint32_t dst, const void* src) {
    asm volatile("cp.async.cg.shared.global [%0], [%1], 16;"
                 :: "r"(dst), "l"(src));
}
__device__ __forceinline__ void cp_commit() {
    asm volatile("cp.async.commit_group;" ::: "memory");
}
template <int N>
__device__ __forceinline__ void cp_wait() {
    asm volatile("cp.async.wait_group %0;" :: "n"(N) : "memory");
}
__device__ __forceinline__ uint32_t f2tf32(float f) {
    uint32_t r;
    asm("cvt.rna.tf32.f32 %0, %1;" : "=r"(r) : "f"(f));
    return r;
}
__device__ __forceinline__ void mma_tf32(float* d, const uint32_t* a,
                                         const uint32_t* b) {
    asm volatile(
        "mma.sync.aligned.m16n8k8.row.col.f32.tf32.tf32.f32 "
        "{%0,%1,%2,%3}, {%4,%5,%6,%7}, {%8,%9}, {%0,%1,%2,%3};"
        : "+f"(d[0]), "+f"(d[1]), "+f"(d[2]), "+f"(d[3])
        : "r"(a[0]), "r"(a[1]), "r"(a[2]), "r"(a[3]), "r"(b[0]), "r"(b[1]));
}

// =======================================================================
// Step 1 (fp32, accuracy-critical root): feats = x @ W_map^T
// 128x64-tile fp32 FFMA2 GEMM (NT), from R2.
// =======================================================================
__global__ __launch_bounds__(256)
void gemm_f32_nt(const float* __restrict__ A, const float* __restrict__ B,
                 float* __restrict__ C, int M, int N, int K)
{
    __shared__ float sAt[16 * 128];
    __shared__ float sBd[16 * 132];

    const int tid = threadIdx.x;
    const int tr  = tid >> 4;
    const int ti  = tid & 15;
    const int m0  = blockIdx.x * 128;
    const int n0  = blockIdx.y * 64;

    unsigned long long acc[4][4];
#pragma unroll
    for (int i = 0; i < 4; i++)
#pragma unroll
        for (int j = 0; j < 4; j++) acc[i][j] = 0ull;

    const int arow = tid & 127;
    const int af   = tid >> 7;

    for (int kb = 0; kb < K; kb += 16) {
        const float* ap = A + (size_t)(m0 + arow) * K + kb + af * 4;
        float4 va0 = *(const float4*)(ap);
        float4 va1 = *(const float4*)(ap + 8);

        int bc = tid >> 2;
        int bk = (tid & 3) * 4;
        float4 vb = *(const float4*)(B + (size_t)(n0 + bc) * K + kb + bk);

        __syncthreads();

        {
            int k0 = af * 4;
            sAt[(k0 + 0) * 128 + arow] = va0.x;
            sAt[(k0 + 1) * 128 + arow] = va0.y;
            sAt[(k0 + 2) * 128 + arow] = va0.z;
            sAt[(k0 + 3) * 128 + arow] = va0.w;
            sAt[(k0 + 8) * 128 + arow] = va1.x;
            sAt[(k0 + 9) * 128 + arow] = va1.y;
            sAt[(k0 +10) * 128 + arow] = va1.z;
            sAt[(k0 +11) * 128 + arow] = va1.w;
        }
        *(float2*)&sBd[(bk + 0) * 132 + 2 * bc] = make_float2(vb.x, vb.x);
        *(float2*)&sBd[(bk + 1) * 132 + 2 * bc] = make_float2(vb.y, vb.y);
        *(float2*)&sBd[(bk + 2) * 132 + 2 * bc] = make_float2(vb.z, vb.z);
        *(float2*)&sBd[(bk + 3) * 132 + 2 * bc] = make_float2(vb.w, vb.w);
        __syncthreads();

#pragma unroll
        for (int k = 0; k < 16; k++) {
            const float* br = sBd + k * 132;
            const float* ar = sAt + k * 128;
            ulonglong2 b01 = *(const ulonglong2*)(br + 8 * ti);
            ulonglong2 b23 = *(const ulonglong2*)(br + 8 * ti + 4);
            ulonglong2 a01 = *(const ulonglong2*)(ar + 8 * tr);
            ulonglong2 a23 = *(const ulonglong2*)(ar + 8 * tr + 4);
            ffma2(acc[0][0], a01.x, b01.x); ffma2(acc[0][1], a01.x, b01.y);
            ffma2(acc[0][2], a01.x, b23.x); ffma2(acc[0][3], a01.x, b23.y);
            ffma2(acc[1][0], a01.y, b01.x); ffma2(acc[1][1], a01.y, b01.y);
            ffma2(acc[1][2], a01.y, b23.x); ffma2(acc[1][3], a01.y, b23.y);
            ffma2(acc[2][0], a23.x, b01.x); ffma2(acc[2][1], a23.x, b01.y);
            ffma2(acc[2][2], a23.x, b23.x); ffma2(acc[2][3], a23.x, b23.y);
            ffma2(acc[3][0], a23.y, b01.x); ffma2(acc[3][1], a23.y, b01.y);
            ffma2(acc[3][2], a23.y, b23.x); ffma2(acc[3][3], a23.y, b23.y);
        }
    }

#pragma unroll
    for (int rp = 0; rp < 4; rp++) {
#pragma unroll
        for (int hh = 0; hh < 2; hh++) {
            int r = 8 * tr + 2 * rp + hh;
            float v0 = hh ? hi32(acc[rp][0]) : lo32(acc[rp][0]);
            float v1 = hh ? hi32(acc[rp][1]) : lo32(acc[rp][1]);
            float v2 = hh ? hi32(acc[rp][2]) : lo32(acc[rp][2]);
            float v3 = hh ? hi32(acc[rp][3]) : lo32(acc[rp][3]);
            size_t base = (size_t)(m0 + r) * N + n0 + 4 * ti;
            *(float4*)(C + base) = make_float4(v0, v1, v2, v3);
        }
    }
}

// =======================================================================
// W_map transpose: WT[v][i] = W[i][v]    (128 x 2048 -> 2048 x 128)
// =======================================================================
__global__ __launch_bounds__(256)
void transpose_wmap(const float* __restrict__ W, float* __restrict__ WT)
{
    __shared__ float t[32][33];
    const int bx = blockIdx.x * 32;   // v
    const int by = blockIdx.y * 32;   // i
    const int tx = threadIdx.x & 31;
    const int ty = threadIdx.x >> 5;  // 0..7
#pragma unroll
    for (int r = 0; r < 32; r += 8)
        t[ty + r][tx] = W[(size_t)(by + ty + r) * VDIM + bx + tx];
    __syncthreads();
#pragma unroll
    for (int r = 0; r < 32; r += 8)
        WT[(size_t)(bx + ty + r) * MDIM + by + tx] = t[tx][ty + r];
}

// =======================================================================
// One-shot tf32 GEMM for K=128 (steps 2 & 5): C = epi(A[M,128] @ B[N,128]^T)
// Full K staged in smem once (stride 132 -> fragment bank = 4*qr+qc, clean).
// 8 warps 2x4; warp tile 64x32 (mt=4, nt=4). EPI: SILU(bias) or RES(X).
// =======================================================================
#define EPI_SILU 1
#define EPI_RES  2
#define GT_SMEM  (2 * 128 * 132 * 4)    // 135168 B

template <int EPI>
__global__ __launch_bounds__(256, 1)
void gemm_tf32_k128(const float* __restrict__ A, const float* __restrict__ B,
                    const float* __restrict__ bias, const float* __restrict__ X,
                    float* __restrict__ C, int N)
{
    extern __shared__ float sm[];
    float* sA = sm;                 // [128][132]
    float* sB = sm + 128 * 132;     // [128][132]
    const uint32_t sA_u = smem_u32(sA);
    const uint32_t sB_u = smem_u32(sB);

    const int tid  = threadIdx.x;
    const int wid  = tid >> 5;
    const int lane = tid & 31;
    const int wr   = wid >> 2;
    const int wc   = wid & 3;
    const int qr   = lane >> 2;
    const int qc   = lane & 3;
    const int m0   = blockIdx.x * 128;
    const int n0   = blockIdx.y * 128;

    // stage A and B fully (K=128: 32 x 16B groups per row)
#pragma unroll
    for (int o = 0; o < 16; o++) {
        int li = o * 256 + tid;
        int row = li >> 5, g = li & 31;
        cp_async16(sA_u + (row * 132 + g * 4) * 4,
                   A + (size_t)(m0 + row) * MDIM + g * 4);
    }
#pragma unroll
    for (int o = 0; o < 16; o++) {
        int li = o * 256 + tid;
        int row = li >> 5, g = li & 31;
        cp_async16(sB_u + (row * 132 + g * 4) * 4,
                   B + (size_t)(n0 + row) * MDIM + g * 4);
    }
    cp_commit();

    float acc[4][4][4];
#pragma unroll
    for (int mt = 0; mt < 4; mt++)
#pragma unroll
        for (int nt = 0; nt < 4; nt++)
#pragma unroll
            for (int v = 0; v < 4; v++) acc[mt][nt][v] = 0.f;

    cp_wait<0>();
    __syncthreads();

#pragma unroll
    for (int k8 = 0; k8 < 16; k8++) {
        const int k0 = k8 * 8;
        uint32_t af[4][4], bf[4][2];
#pragma unroll
        for (int mt = 0; mt < 4; mt++) {
            const float* ar = sA + (wr * 64 + mt * 16 + qr) * 132 + k0 + qc;
            af[mt][0] = f2tf32(ar[0]);
            af[mt][1] = f2tf32(ar[8 * 132]);
            af[mt][2] = f2tf32(ar[4]);
            af[mt][3] = f2tf32(ar[8 * 132 + 4]);
        }
#pragma unroll
        for (int nt = 0; nt < 4; nt++) {
            const float* br = sB + (wc * 32 + nt * 8 + qr) * 132 + k0 + qc;
            bf[nt][0] = f2tf32(br[0]);
            bf[nt][1] = f2tf32(br[4]);
        }
#pragma unroll
        for (int mt = 0; mt < 4; mt++)
#pragma unroll
            for (int nt = 0; nt < 4; nt++)
                mma_tf32(acc[mt][nt], af[mt], bf[nt]);
    }

    // epilogue: direct global stores (float2 per fragment half)
#pragma unroll
    for (int mt = 0; mt < 4; mt++) {
#pragma unroll
        for (int nt = 0; nt < 4; nt++) {
            int col = n0 + wc * 32 + nt * 8 + 2 * qc;
#pragma unroll
            for (int h2 = 0; h2 < 2; h2++) {
                int row = m0 + wr * 64 + mt * 16 + qr + 8 * h2;
                float v0 = acc[mt][nt][2 * h2];
                float v1 = acc[mt][nt][2 * h2 + 1];
                size_t base = (size_t)row * N + col;
                float2 o;
                if (EPI == EPI_SILU) {
                    float z0 = v0 + bias[col];
                    float z1 = v1 + bias[col + 1];
                    o.x = z0 / (1.f + expf(-z0));
                    o.y = z1 / (1.f + expf(-z1));
                } else {
                    float2 xv = *(const float2*)(X + base);
                    o.x = v0 + xv.x;
                    o.y = v1 + xv.y;
                }
                *(float2*)(C + base) = o;
            }
        }
    }
}

// =======================================================================
// K3 via legacy mma.sync (tf32):
//   C1[n, i*128+j] = sum_k h[n,k] * W2[(i*128+j), k]     (NT GEMM, K=512)
//   feats2[n,i]    = sum_j (C1[n,ij] + b2[ij]) * feats[n,j]   (epilogue)
// 3-stage cp.async ring, ONE __syncthreads per chunk.
// CTA 128x256, warp tile 64x64 (4mt x 8nt), stride-36 smem.
// =======================================================================
#define K3_BM   128
#define K3_BN   256
#define K3_KC   32
#define K3_NCH  16
#define K3_ASTR 36
#define K3_ASTG (K3_BM * K3_ASTR)          // 4608 floats
#define K3_BSTG (K3_BN * K3_ASTR)          // 9216 floats
#define K3_SMEM_BYTES (3 * (K3_ASTG + K3_BSTG) * 4 + 2048)   // 167936 B

__global__ __launch_bounds__(256, 1)
void k3_mma(const float* __restrict__ W2,
            const float* __restrict__ feats,
            const float* __restrict__ h,
            const float* __restrict__ b2,
            float* __restrict__ feats2)
{
    extern __shared__ float smf[];
    float* sAf  = smf;                                    // [3][4608]
    float* sBf  = smf + 3 * K3_ASTG;                      // [3][9216]
    float* sRed = smf + 3 * (K3_ASTG + K3_BSTG);          // [128][4]
    const uint32_t sA_u = smem_u32(sAf);
    const uint32_t sB_u = smem_u32(sBf);

    const int tid  = threadIdx.x;
    const int wid  = tid >> 5;
    const int lane = tid & 31;
    const int wr   = wid >> 2;
    const int wc   = wid & 3;
    const int qr   = lane >> 2;
    const int qc   = lane & 3;
    const int m0   = blockIdx.x * K3_BM;
    const int nb   = blockIdx.y;

    float acc[4][8][4];
#pragma unroll
    for (int mt = 0; mt < 4; mt++)
#pragma unroll
        for (int nt = 0; nt < 8; nt++)
#pragma unroll
            for (int v = 0; v < 4; v++) acc[mt][nt][v] = 0.f;

    auto load_chunk = [&](int c) {
        const int s = c % 3;
        const int kc = c * K3_KC;
        const uint32_t ab = sA_u + s * K3_ASTG * 4;
        const uint32_t bb = sB_u + s * K3_BSTG * 4;
#pragma unroll
        for (int o = 0; o < 4; o++) {
            int li = o * 256 + tid;
            int row = li >> 3, g = li & 7;
            cp_async16(ab + (row * K3_ASTR + g * 4) * 4,
                       h + (size_t)(m0 + row) * HDIM + kc + g * 4);
        }
#pragma unroll
        for (int o = 0; o < 8; o++) {
            int li = o * 256 + tid;
            int row = li >> 3, g = li & 7;
            cp_async16(bb + (row * K3_ASTR + g * 4) * 4,
                       W2 + (size_t)(nb * K3_BN + row) * HDIM + kc + g * 4);
        }
        cp_commit();
    };

    load_chunk(0);
    load_chunk(1);

    for (int c = 0; c < K3_NCH; c++) {
        if (c < K3_NCH - 1) cp_wait<1>();
        else                cp_wait<0>();
        __syncthreads();            // chunk c visible; everyone past chunk c-1 MMAs
        if (c + 2 < K3_NCH) load_chunk(c + 2);   // overwrites buffer (c-1)%3: safe

        const float* A = sAf + (c % 3) * K3_ASTG;
        const float* B = sBf + (c % 3) * K3_BSTG;

#pragma unroll
        for (int k8 = 0; k8 < 4; k8++) {
            const int k0 = k8 * 8;
            uint32_t af[4][4], bf[8][2];
#pragma unroll
            for (int mt = 0; mt < 4; mt++) {
                const float* ar = A + (wr * 64 + mt * 16 + qr) * K3_ASTR + k0 + qc;
                af[mt][0] = f2tf32(ar[0]);
                af[mt][1] = f2tf32(ar[8 * K3_ASTR]);
                af[mt][2] = f2tf32(ar[4]);
                af[mt][3] = f2tf32(ar[8 * K3_ASTR + 4]);
            }
#pragma unroll
            for (int nt = 0; nt < 8; nt++) {
                const float* br = B + (wc * 64 + nt * 8 + qr) * K3_ASTR + k0 + qc;
                bf[nt][0] = f2tf32(br[0]);
                bf[nt][1] = f2tf32(br[4]);
            }
#pragma unroll
            for (int mt = 0; mt < 4; mt++)
#pragma unroll
                for (int nt = 0; nt < 8; nt++)
                    mma_tf32(acc[mt][nt], af[mt], bf[nt]);
        }
    }
    __syncthreads();   // all MMAs done before smem reuse below

    // ---- epilogue: stage feats [128][132], reduce over j ----
    float* fs = sAf;
#pragma unroll
    for (int o = 0; o < 16; o++) {
        int li = o * 256 + tid;
        int row = li >> 5, g = li & 31;
        float4 v = *(const float4*)(feats + (size_t)(m0 + row) * MDIM + g * 4);
        float* d = fs + row * 132 + g * 4;
        d[0] = v.x; d[1] = v.y; d[2] = v.z; d[3] = v.w;
    }
    __syncthreads();

#pragma unroll
    for (int mt = 0; mt < 4; mt++) {
#pragma unroll
        for (int h2 = 0; h2 < 2; h2++) {
            int rl = wr * 64 + mt * 16 + qr + 8 * h2;
            float p = 0.f;
#pragma unroll
            for (int nt = 0; nt < 8; nt++) {
                int j0 = (wc & 1) * 64 + nt * 8 + 2 * qc;
                p = fmaf(acc[mt][nt][2 * h2],     fs[rl * 132 + j0],     p);
                p = fmaf(acc[mt][nt][2 * h2 + 1], fs[rl * 132 + j0 + 1], p);
            }
            p += __shfl_xor_sync(0xffffffffu, p, 1);
            p += __shfl_xor_sync(0xffffffffu, p, 2);
            if (qc == 0) sRed[rl * 4 + wc] = p;
        }
    }
    __syncthreads();

    {
        int row = tid >> 1, iv = tid & 1;
        float s = sRed[row * 4 + iv * 2] + sRed[row * 4 + iv * 2 + 1];
        // fold b2 bias term: + sum_j b2[(2nb+iv)*128 + j] * feats[row][j]
        const float4* bb = (const float4*)(b2 + (size_t)(nb * 2 + iv) * MDIM);
        const float* fr = fs + row * 132;
        float bacc = 0.f;
#pragma unroll
        for (int j = 0; j < 32; j++) {
            float4 v = bb[j];
            bacc = fmaf(v.x, fr[4 * j + 0],
                   fmaf(v.y, fr[4 * j + 1],
                   fmaf(v.z, fr[4 * j + 2],
                   fmaf(v.w, fr[4 * j + 3], bacc))));
        }
        feats2[(size_t)(m0 + row) * MDIM + nb * 2 + iv] = s + bacc;
    }
}

// =======================================================================
// Host launcher
// =======================================================================
extern "C" void kernel_launch(void* const* d_in, const int* in_sizes, int n_in,
                              void* d_out, int out_size)
{
    const float* x    = (const float*)d_in[0];
    const float* Wmap = (const float*)d_in[1];
    const float* W1   = (const float*)d_in[2];
    const float* b1   = (const float*)d_in[3];
    const float* W2   = (const float*)d_in[4];
    const float* b2   = (const float*)d_in[5];
    float* out = (float*)d_out;

    void *pf, *ph, *pf2, *pwt;
    cudaGetSymbolAddress(&pf,  g_feats);
    cudaGetSymbolAddress(&ph,  g_h);
    cudaGetSymbolAddress(&pf2, g_feats2);
    cudaGetSymbolAddress(&pwt, g_wmapT);
    float* feats  = (float*)pf;
    float* hbuf   = (float*)ph;
    float* feats2 = (float*)pf2;
    float* wmapT  = (float*)pwt;

    cudaFuncSetAttribute(k3_mma, cudaFuncAttributeMaxDynamicSharedMemorySize,
                         K3_SMEM_BYTES);
    cudaFuncSetAttribute(gemm_tf32_k128<EPI_SILU>,
                         cudaFuncAttributeMaxDynamicSharedMemorySize, GT_SMEM);
    cudaFuncSetAttribute(gemm_tf32_k128<EPI_RES>,
                         cudaFuncAttributeMaxDynamicSharedMemorySize, GT_SMEM);

    dim3 blk(256);

    // 0) WmapT = W_map^T   (for step 5's NT form)
    transpose_wmap<<<dim3(VDIM / 32, MDIM / 32), blk>>>(Wmap, wmapT);

    // 1) feats = x @ W_map^T          (fp32, M=8192, N=128, K=2048)
    gemm_f32_nt<<<dim3(NROWS / 128, MDIM / 64), blk>>>(
        x, Wmap, feats, NROWS, MDIM, VDIM);

    // 2) h = silu(feats @ W1^T + b1)  (tf32, M=8192, N=512, K=128)
    gemm_tf32_k128<EPI_SILU><<<dim3(NROWS / 128, HDIM / 128), blk, GT_SMEM>>>(
        feats, W1, b1, nullptr, hbuf, HDIM);

    // 3+4) feats2 = ((h @ W2^T) + b2-term) . feats   (tf32 core, bias folded)
    k3_mma<<<dim3(NROWS / K3_BM, 16384 / K3_BN), blk, K3_SMEM_BYTES>>>(
        W2, feats, hbuf, b2, feats2);

    // 5) out = x + feats2 @ WmapT^T   (tf32, M=8192, N=2048, K=128)
    gemm_tf32_k128<EPI_RES><<<dim3(NROWS / 128, VDIM / 128), blk, GT_SMEM>>>(
        feats2, wmapT, nullptr, x, out, VDIM);
}

// round 9
// speedup vs baseline: 4.2274x; 1.1069x over previous
#include <cuda_runtime.h>
#include <cstdint>
#include <cstdio>

// Problem dims (fixed)
#define NROWS 8192
#define VDIM  2048
#define MDIM  128
#define HDIM  512

// Scratch (allocation-free rule: __device__ globals)
__device__ __align__(256) float g_feats [NROWS * MDIM];     // 4 MB
__device__ __align__(256) float g_h     [NROWS * HDIM];     // 16 MB (tf32-rounded)
__device__ __align__(256) float g_feats2[NROWS * MDIM];     // 4 MB (tf32-rounded)
__device__ __align__(256) float g_wmapT [VDIM * MDIM];      // 1 MB (tf32-rounded)
__device__ __align__(256) float g_w2r   [MDIM * MDIM * HDIM]; // 64 MB (tf32-rounded W2)
__device__ __align__(256) float g_w1r   [4 * MDIM * MDIM];  // 256 KB (tf32-rounded W1)

// ---------------- packed fp32 helpers ----------------
__device__ __forceinline__ void ffma2(unsigned long long& d,
                                      unsigned long long a,
                                      unsigned long long b) {
    asm volatile("fma.rn.f32x2 %0, %1, %2, %0;" : "+l"(d) : "l"(a), "l"(b));
}
__device__ __forceinline__ float lo32(unsigned long long v) {
    return __uint_as_float((unsigned)(v & 0xffffffffull));
}
__device__ __forceinline__ float hi32(unsigned long long v) {
    return __uint_as_float((unsigned)(v >> 32));
}

// ---------------- common PTX helpers ----------------
__device__ __forceinline__ uint32_t smem_u32(const void* p) {
    uint32_t a;
    asm("{ .reg .u64 t; cvta.to.shared.u64 t, %1; cvt.u32.u64 %0, t; }"
        : "=r"(a) : "l"(p));
    return a;
}
__device__ __forceinline__ void cp_async16(uint32_t dst, const void* src) {
    asm volatile("cp.async.cg.shared.global [%0], [%1], 16;"
                 :: "r"(dst), "l"(src));
}
__device__ __forceinline__ void cp_commit() {
    asm volatile("cp.async.commit_group;" ::: "memory");
}
template <int N>
__device__ __forceinline__ void cp_wait() {
    asm volatile("cp.async.wait_group %0;" :: "n"(N) : "memory");
}
__device__ __forceinline__ uint32_t f2tf32(float f) {
    uint32_t r;
    asm("cvt.rna.tf32.f32 %0, %1;" : "=r"(r) : "f"(f));
    return r;
}
__device__ __forceinline__ void mma_tf32(float* d, const uint32_t* a,
                                         const uint32_t* b) {
    asm volatile(
        "mma.sync.aligned.m16n8k8.row.col.f32.tf32.tf32.f32 "
        "{%0,%1,%2,%3}, {%4,%5,%6,%7}, {%8,%9}, {%0,%1,%2,%3};"
        : "+f"(d[0]), "+f"(d[1]), "+f"(d[2]), "+f"(d[3])
        : "r"(a[0]), "r"(a[1]), "r"(a[2]), "r"(a[3]), "r"(b[0]), "r"(b[1]));
}
// ldmatrix x4: one 8x8-b16 (== 8x4-b32) tile per 8-lane group; 4 regs/lane out.
__device__ __forceinline__ void ldsm_x4(uint32_t& r0, uint32_t& r1,
                                        uint32_t& r2, uint32_t& r3,
                                        uint32_t addr) {
    asm volatile("ldmatrix.sync.aligned.m8n8.x4.shared.b16 {%0,%1,%2,%3}, [%4];"
                 : "=r"(r0), "=r"(r1), "=r"(r2), "=r"(r3) : "r"(addr));
}

// =======================================================================
// Pre-round a buffer to tf32 format (float bits with rounded mantissa)
// =======================================================================
__global__ __launch_bounds__(256)
void round_tf32_kernel(const float4* __restrict__ in, float4* __restrict__ out,
                       int n4)
{
    int i = blockIdx.x * blockDim.x + threadIdx.x;
    int stride = gridDim.x * blockDim.x;
    for (; i < n4; i += stride) {
        float4 v = in[i];
        float4 o;
        o.x = __uint_as_float(f2tf32(v.x));
        o.y = __uint_as_float(f2tf32(v.y));
        o.z = __uint_as_float(f2tf32(v.z));
        o.w = __uint_as_float(f2tf32(v.w));
        out[i] = o;
    }
}

// =======================================================================
// Step 1 (fp32, accuracy-critical root): feats = x @ W_map^T
// =======================================================================
__global__ __launch_bounds__(256)
void gemm_f32_nt(const float* __restrict__ A, const float* __restrict__ B,
                 float* __restrict__ C, int M, int N, int K)
{
    __shared__ float sAt[16 * 128];
    __shared__ float sBd[16 * 132];

    const int tid = threadIdx.x;
    const int tr  = tid >> 4;
    const int ti  = tid & 15;
    const int m0  = blockIdx.x * 128;
    const int n0  = blockIdx.y * 64;

    unsigned long long acc[4][4];
#pragma unroll
    for (int i = 0; i < 4; i++)
#pragma unroll
        for (int j = 0; j < 4; j++) acc[i][j] = 0ull;

    const int arow = tid & 127;
    const int af   = tid >> 7;

    for (int kb = 0; kb < K; kb += 16) {
        const float* ap = A + (size_t)(m0 + arow) * K + kb + af * 4;
        float4 va0 = *(const float4*)(ap);
        float4 va1 = *(const float4*)(ap + 8);

        int bc = tid >> 2;
        int bk = (tid & 3) * 4;
        float4 vb = *(const float4*)(B + (size_t)(n0 + bc) * K + kb + bk);

        __syncthreads();

        {
            int k0 = af * 4;
            sAt[(k0 + 0) * 128 + arow] = va0.x;
            sAt[(k0 + 1) * 128 + arow] = va0.y;
            sAt[(k0 + 2) * 128 + arow] = va0.z;
            sAt[(k0 + 3) * 128 + arow] = va0.w;
            sAt[(k0 + 8) * 128 + arow] = va1.x;
            sAt[(k0 + 9) * 128 + arow] = va1.y;
            sAt[(k0 +10) * 128 + arow] = va1.z;
            sAt[(k0 +11) * 128 + arow] = va1.w;
        }
        *(float2*)&sBd[(bk + 0) * 132 + 2 * bc] = make_float2(vb.x, vb.x);
        *(float2*)&sBd[(bk + 1) * 132 + 2 * bc] = make_float2(vb.y, vb.y);
        *(float2*)&sBd[(bk + 2) * 132 + 2 * bc] = make_float2(vb.z, vb.z);
        *(float2*)&sBd[(bk + 3) * 132 + 2 * bc] = make_float2(vb.w, vb.w);
        __syncthreads();

#pragma unroll
        for (int k = 0; k < 16; k++) {
            const float* br = sBd + k * 132;
            const float* ar = sAt + k * 128;
            ulonglong2 b01 = *(const ulonglong2*)(br + 8 * ti);
            ulonglong2 b23 = *(const ulonglong2*)(br + 8 * ti + 4);
            ulonglong2 a01 = *(const ulonglong2*)(ar + 8 * tr);
            ulonglong2 a23 = *(const ulonglong2*)(ar + 8 * tr + 4);
            ffma2(acc[0][0], a01.x, b01.x); ffma2(acc[0][1], a01.x, b01.y);
            ffma2(acc[0][2], a01.x, b23.x); ffma2(acc[0][3], a01.x, b23.y);
            ffma2(acc[1][0], a01.y, b01.x); ffma2(acc[1][1], a01.y, b01.y);
            ffma2(acc[1][2], a01.y, b23.x); ffma2(acc[1][3], a01.y, b23.y);
            ffma2(acc[2][0], a23.x, b01.x); ffma2(acc[2][1], a23.x, b01.y);
            ffma2(acc[2][2], a23.x, b23.x); ffma2(acc[2][3], a23.x, b23.y);
            ffma2(acc[3][0], a23.y, b01.x); ffma2(acc[3][1], a23.y, b01.y);
            ffma2(acc[3][2], a23.y, b23.x); ffma2(acc[3][3], a23.y, b23.y);
        }
    }

#pragma unroll
    for (int rp = 0; rp < 4; rp++) {
#pragma unroll
        for (int hh = 0; hh < 2; hh++) {
            int r = 8 * tr + 2 * rp + hh;
            float v0 = hh ? hi32(acc[rp][0]) : lo32(acc[rp][0]);
            float v1 = hh ? hi32(acc[rp][1]) : lo32(acc[rp][1]);
            float v2 = hh ? hi32(acc[rp][2]) : lo32(acc[rp][2]);
            float v3 = hh ? hi32(acc[rp][3]) : lo32(acc[rp][3]);
            size_t base = (size_t)(m0 + r) * N + n0 + 4 * ti;
            *(float4*)(C + base) = make_float4(v0, v1, v2, v3);
        }
    }
}

// =======================================================================
// W_map transpose (+ tf32 round): WT[v][i] = round(W[i][v])
// =======================================================================
__global__ __launch_bounds__(256)
void transpose_wmap(const float* __restrict__ W, float* __restrict__ WT)
{
    __shared__ float t[32][33];
    const int bx = blockIdx.x * 32;   // v
    const int by = blockIdx.y * 32;   // i
    const int tx = threadIdx.x & 31;
    const int ty = threadIdx.x >> 5;  // 0..7
#pragma unroll
    for (int r = 0; r < 32; r += 8)
        t[ty + r][tx] = W[(size_t)(by + ty + r) * VDIM + bx + tx];
    __syncthreads();
#pragma unroll
    for (int r = 0; r < 32; r += 8)
        WT[(size_t)(bx + ty + r) * MDIM + by + tx] =
            __uint_as_float(f2tf32(t[tx][ty + r]));
}

// =======================================================================
// One-shot tf32 GEMM for K=128 (steps 2 & 5): C = epi(A[M,128] @ B[N,128]^T)
// B pre-rounded (raw loads); A cvt'd iff CVTA.
// =======================================================================
#define EPI_SILU 1
#define EPI_RES  2
#define GT_SMEM  (2 * 128 * 132 * 4)    // 135168 B

template <int EPI, bool CVTA>
__global__ __launch_bounds__(256, 1)
void gemm_tf32_k128(const float* __restrict__ A, const float* __restrict__ B,
                    const float* __restrict__ bias, const float* __restrict__ X,
                    float* __restrict__ C, int N)
{
    extern __shared__ float sm[];
    float* sA = sm;                 // [128][132]
    float* sB = sm + 128 * 132;     // [128][132]
    const uint32_t sA_u = smem_u32(sA);
    const uint32_t sB_u = smem_u32(sB);

    const int tid  = threadIdx.x;
    const int wid  = tid >> 5;
    const int lane = tid & 31;
    const int wr   = wid >> 2;
    const int wc   = wid & 3;
    const int qr   = lane >> 2;
    const int qc   = lane & 3;
    const int m0   = blockIdx.x * 128;
    const int n0   = blockIdx.y * 128;

#pragma unroll
    for (int o = 0; o < 16; o++) {
        int li = o * 256 + tid;
        int row = li >> 5, g = li & 31;
        cp_async16(sA_u + (row * 132 + g * 4) * 4,
                   A + (size_t)(m0 + row) * MDIM + g * 4);
    }
#pragma unroll
    for (int o = 0; o < 16; o++) {
        int li = o * 256 + tid;
        int row = li >> 5, g = li & 31;
        cp_async16(sB_u + (row * 132 + g * 4) * 4,
                   B + (size_t)(n0 + row) * MDIM + g * 4);
    }
    cp_commit();

    float acc[4][4][4];
#pragma unroll
    for (int mt = 0; mt < 4; mt++)
#pragma unroll
        for (int nt = 0; nt < 4; nt++)
#pragma unroll
            for (int v = 0; v < 4; v++) acc[mt][nt][v] = 0.f;

    cp_wait<0>();
    __syncthreads();

#pragma unroll
    for (int k8 = 0; k8 < 16; k8++) {
        const int k0 = k8 * 8;
        uint32_t af[4][4], bf[4][2];
#pragma unroll
        for (int mt = 0; mt < 4; mt++) {
            const float* ar = sA + (wr * 64 + mt * 16 + qr) * 132 + k0 + qc;
            if (CVTA) {
                af[mt][0] = f2tf32(ar[0]);
                af[mt][1] = f2tf32(ar[8 * 132]);
                af[mt][2] = f2tf32(ar[4]);
                af[mt][3] = f2tf32(ar[8 * 132 + 4]);
            } else {
                af[mt][0] = __float_as_uint(ar[0]);
                af[mt][1] = __float_as_uint(ar[8 * 132]);
                af[mt][2] = __float_as_uint(ar[4]);
                af[mt][3] = __float_as_uint(ar[8 * 132 + 4]);
            }
        }
#pragma unroll
        for (int nt = 0; nt < 4; nt++) {
            const float* br = sB + (wc * 32 + nt * 8 + qr) * 132 + k0 + qc;
            bf[nt][0] = __float_as_uint(br[0]);
            bf[nt][1] = __float_as_uint(br[4]);
        }
#pragma unroll
        for (int mt = 0; mt < 4; mt++)
#pragma unroll
            for (int nt = 0; nt < 4; nt++)
                mma_tf32(acc[mt][nt], af[mt], bf[nt]);
    }

#pragma unroll
    for (int mt = 0; mt < 4; mt++) {
#pragma unroll
        for (int nt = 0; nt < 4; nt++) {
            int col = n0 + wc * 32 + nt * 8 + 2 * qc;
#pragma unroll
            for (int h2 = 0; h2 < 2; h2++) {
                int row = m0 + wr * 64 + mt * 16 + qr + 8 * h2;
                float v0 = acc[mt][nt][2 * h2];
                float v1 = acc[mt][nt][2 * h2 + 1];
                size_t base = (size_t)row * N + col;
                float2 o;
                if (EPI == EPI_SILU) {
                    float z0 = v0 + bias[col];
                    float z1 = v1 + bias[col + 1];
                    o.x = __uint_as_float(f2tf32(z0 / (1.f + expf(-z0))));
                    o.y = __uint_as_float(f2tf32(z1 / (1.f + expf(-z1))));
                } else {
                    float2 xv = *(const float2*)(X + base);
                    o.x = v0 + xv.x;
                    o.y = v1 + xv.y;
                }
                *(float2*)(C + base) = o;
            }
        }
    }
}

// =======================================================================
// K3 (tf32 mma.sync + ldmatrix; operands pre-rounded in gmem):
//   C1[n, i*128+j] = sum_k h[n,k] * W2r[(i*128+j), k]    (NT GEMM, K=512)
//   feats2[n,i]    = round_tf32( sum_j (C1 + b2-term) * feats[n,j] )
// KC=64, 2-stage ring, one __syncthreads per chunk.
// Inner loop per k8: 4 LDSM.x4 (A) + 4 LDSM.x4 (B) + 32 MMA — no LDS, no CVT.
// Stride 68 floats (68%32==4): each 8-row LDSM phase covers all 32 banks.
// =======================================================================
#define K3_BM   128
#define K3_BN   256
#define K3_KC   64
#define K3_NCH  8                          // 512 / 64
#define K3_STR  68
#define K3_ASTG (K3_BM * K3_STR)           // 8704 floats
#define K3_BSTG (K3_BN * K3_STR)           // 17408 floats
#define K3_SMEM_BYTES (2 * (K3_ASTG + K3_BSTG) * 4 + 2048)   // 210944 B

__global__ __launch_bounds__(256, 1)
void k3_mma(const float* __restrict__ W2r,
            const float* __restrict__ feats,
            const float* __restrict__ h,
            const float* __restrict__ b2,
            float* __restrict__ feats2)
{
    extern __shared__ float smf[];
    float* sAf  = smf;                                    // [2][8704]
    float* sBf  = smf + 2 * K3_ASTG;                      // [2][17408]
    float* sRed = smf + 2 * (K3_ASTG + K3_BSTG);          // [128][4]
    const uint32_t sA_u = smem_u32(sAf);
    const uint32_t sB_u = smem_u32(sBf);

    const int tid  = threadIdx.x;
    const int wid  = tid >> 5;
    const int lane = tid & 31;
    const int wr   = wid >> 2;
    const int wc   = wid & 3;
    const int qr   = lane >> 2;
    const int qc   = lane & 3;
    const int m0   = blockIdx.x * K3_BM;
    const int nb   = blockIdx.y;

    // per-lane ldmatrix tile/row decomposition
    const int lt = lane >> 3;          // tile index 0..3 within x4
    const int lr = lane & 7;           // row within tile
    // A tiles for warp-tile mt: t0=(row+0,k+0)->a0, t1=(row+8,k+0)->a1,
    //                           t2=(row+0,k+4)->a2, t3=(row+8,k+4)->a3
    const int a_off = (wr * 64 + (lt & 1) * 8 + lr) * K3_STR + (lt >> 1) * 4;
    // B tiles for nt-pair p:    t0=(n+0,k+0)->bf[2p][0], t1=(n+0,k+4)->bf[2p][1],
    //                           t2=(n+8,k+0)->bf[2p+1][0], t3=(n+8,k+4)->bf[2p+1][1]
    const int b_off = (wc * 64 + (lt >> 1) * 8 + lr) * K3_STR + (lt & 1) * 4;

    float acc[4][8][4];
#pragma unroll
    for (int mt = 0; mt < 4; mt++)
#pragma unroll
        for (int nt = 0; nt < 8; nt++)
#pragma unroll
            for (int v = 0; v < 4; v++) acc[mt][nt][v] = 0.f;

    // chunk = KC=64 cols: A 128 rows x 16 granules, B 256 rows x 16 granules
    auto load_chunk = [&](int c) {
        const int s = c & 1;
        const int kc = c * K3_KC;
        const uint32_t ab = sA_u + s * K3_ASTG * 4;
        const uint32_t bb = sB_u + s * K3_BSTG * 4;
#pragma unroll
        for (int o = 0; o < 8; o++) {                 // 128*16 = 2048 tasks
            int li = o * 256 + tid;
            int row = li >> 4, g = li & 15;
            cp_async16(ab + (row * K3_STR + g * 4) * 4,
                       h + (size_t)(m0 + row) * HDIM + kc + g * 4);
        }
#pragma unroll
        for (int o = 0; o < 16; o++) {                // 256*16 = 4096 tasks
            int li = o * 256 + tid;
            int row = li >> 4, g = li & 15;
            cp_async16(bb + (row * K3_STR + g * 4) * 4,
                       W2r + (size_t)(nb * K3_BN + row) * HDIM + kc + g * 4);
        }
        cp_commit();
    };

    load_chunk(0);

    for (int c = 0; c < K3_NCH; c++) {
        cp_wait<0>();            // chunk c landed
        __syncthreads();         // all warps past chunk c-1 MMAs; data visible
        if (c + 1 < K3_NCH) load_chunk(c + 1);   // overlaps compute below

        const uint32_t ab = sA_u + (c & 1) * K3_ASTG * 4;
        const uint32_t bb = sB_u + (c & 1) * K3_BSTG * 4;

#pragma unroll
        for (int k8 = 0; k8 < 8; k8++) {
            const int k0 = k8 * 8;
            uint32_t af[4][4], bf[8][2];
#pragma unroll
            for (int mt = 0; mt < 4; mt++)
                ldsm_x4(af[mt][0], af[mt][1], af[mt][2], af[mt][3],
                        ab + (uint32_t)(a_off + mt * 16 * K3_STR + k0) * 4);
#pragma unroll
            for (int p = 0; p < 4; p++) {
                uint32_t r0, r1, r2, r3;
                ldsm_x4(r0, r1, r2, r3,
                        bb + (uint32_t)(b_off + p * 16 * K3_STR + k0) * 4);
                bf[2 * p][0] = r0;  bf[2 * p][1] = r1;
                bf[2 * p + 1][0] = r2;  bf[2 * p + 1][1] = r3;
            }
#pragma unroll
            for (int mt = 0; mt < 4; mt++)
#pragma unroll
                for (int nt = 0; nt < 8; nt++)
                    mma_tf32(acc[mt][nt], af[mt], bf[nt]);
        }
    }
    __syncthreads();   // all MMAs done before smem reuse below

    // ---- epilogue: stage feats [128][132], reduce over j ----
    float* fs = sAf;
#pragma unroll
    for (int o = 0; o < 16; o++) {
        int li = o * 256 + tid;
        int row = li >> 5, g = li & 31;
        float4 v = *(const float4*)(feats + (size_t)(m0 + row) * MDIM + g * 4);
        float* d = fs + row * 132 + g * 4;
        d[0] = v.x; d[1] = v.y; d[2] = v.z; d[3] = v.w;
    }
    __syncthreads();

#pragma unroll
    for (int mt = 0; mt < 4; mt++) {
#pragma unroll
        for (int h2 = 0; h2 < 2; h2++) {
            int rl = wr * 64 + mt * 16 + qr + 8 * h2;
            float p = 0.f;
#pragma unroll
            for (int nt = 0; nt < 8; nt++) {
                int j0 = (wc & 1) * 64 + nt * 8 + 2 * qc;
                p = fmaf(acc[mt][nt][2 * h2],     fs[rl * 132 + j0],     p);
                p = fmaf(acc[mt][nt][2 * h2 + 1], fs[rl * 132 + j0 + 1], p);
            }
            p += __shfl_xor_sync(0xffffffffu, p, 1);
            p += __shfl_xor_sync(0xffffffffu, p, 2);
            if (qc == 0) sRed[rl * 4 + wc] = p;
        }
    }
    __syncthreads();

    {
        int row = tid >> 1, iv = tid & 1;
        float s = sRed[row * 4 + iv * 2] + sRed[row * 4 + iv * 2 + 1];
        // fold b2 bias term: + sum_j b2[(2nb+iv)*128 + j] * feats[row][j]
        const float4* bb2 = (const float4*)(b2 + (size_t)(nb * 2 + iv) * MDIM);
        const float* fr = fs + row * 132;
        float bacc = 0.f;
#pragma unroll
        for (int j = 0; j < 32; j++) {
            float4 v = bb2[j];
            bacc = fmaf(v.x, fr[4 * j + 0],
                   fmaf(v.y, fr[4 * j + 1],
                   fmaf(v.z, fr[4 * j + 2],
                   fmaf(v.w, fr[4 * j + 3], bacc))));
        }
        // store tf32-rounded (only consumer is step 5's MMA which rounds anyway)
        feats2[(size_t)(m0 + row) * MDIM + nb * 2 + iv] =
            __uint_as_float(f2tf32(s + bacc));
    }
}

// =======================================================================
// Host launcher
// =======================================================================
extern "C" void kernel_launch(void* const* d_in, const int* in_sizes, int n_in,
                              void* d_out, int out_size)
{
    const float* x    = (const float*)d_in[0];
    const float* Wmap = (const float*)d_in[1];
    const float* W1   = (const float*)d_in[2];
    const float* b1   = (const float*)d_in[3];
    const float* W2   = (const float*)d_in[4];
    const float* b2   = (const float*)d_in[5];
    float* out = (float*)d_out;

    void *pf, *ph, *pf2, *pwt, *pw2, *pw1;
    cudaGetSymbolAddress(&pf,  g_feats);
    cudaGetSymbolAddress(&ph,  g_h);
    cudaGetSymbolAddress(&pf2, g_feats2);
    cudaGetSymbolAddress(&pwt, g_wmapT);
    cudaGetSymbolAddress(&pw2, g_w2r);
    cudaGetSymbolAddress(&pw1, g_w1r);
    float* feats  = (float*)pf;
    float* hbuf   = (float*)ph;
    float* feats2 = (float*)pf2;
    float* wmapT  = (float*)pwt;
    float* w2r    = (float*)pw2;
    float* w1r    = (float*)pw1;

    cudaFuncSetAttribute(k3_mma, cudaFuncAttributeMaxDynamicSharedMemorySize,
                         K3_SMEM_BYTES);
    cudaFuncSetAttribute(gemm_tf32_k128<EPI_SILU, true>,
                         cudaFuncAttributeMaxDynamicSharedMemorySize, GT_SMEM);
    cudaFuncSetAttribute(gemm_tf32_k128<EPI_RES, false>,
                         cudaFuncAttributeMaxDynamicSharedMemorySize, GT_SMEM);

    dim3 blk(256);

    // 0a) pre-round W2 (16.78M elems), W1 (65.5K) to tf32 format
    round_tf32_kernel<<<2048, blk>>>((const float4*)W2, (float4*)w2r,
                                     MDIM * MDIM * HDIM / 4);
    round_tf32_kernel<<<64, blk>>>((const float4*)W1, (float4*)w1r,
                                   4 * MDIM * MDIM / 4);
    // 0b) WmapT = round(W_map^T)
    transpose_wmap<<<dim3(VDIM / 32, MDIM / 32), blk>>>(Wmap, wmapT);

    // 1) feats = x @ W_map^T          (fp32, M=8192, N=128, K=2048)
    gemm_f32_nt<<<dim3(NROWS / 128, MDIM / 64), blk>>>(
        x, Wmap, feats, NROWS, MDIM, VDIM);

    // 2) h = round(silu(feats @ W1^T + b1))  (tf32, M=8192, N=512, K=128)
    gemm_tf32_k128<EPI_SILU, true><<<dim3(NROWS / 128, HDIM / 128), blk, GT_SMEM>>>(
        feats, w1r, b1, nullptr, hbuf, HDIM);

    // 3+4) feats2 = round(((h @ W2r^T) + b2-term) . feats)   (ldmatrix + mma)
    k3_mma<<<dim3(NROWS / K3_BM, 16384 / K3_BN), blk, K3_SMEM_BYTES>>>(
        w2r, feats, hbuf, b2, feats2);

    // 5) out = x + feats2 @ wmapT^T   (tf32, M=8192, N=2048, K=128; no cvts)
    gemm_tf32_k128<EPI_RES, false><<<dim3(NROWS / 128, VDIM / 128), blk, GT_SMEM>>>(
        feats2, wmapT, nullptr, x, out, VDIM);
}

// round 10
// speedup vs baseline: 4.7598x; 1.1259x over previous
#include <cuda_runtime.h>
#include <cstdint>
#include <cstdio>

// Problem dims (fixed)
#define NROWS 8192
#define VDIM  2048
#define MDIM  128
#define HDIM  512

// Scratch (allocation-free rule: __device__ globals)
__device__ __align__(256) float g_feats [NROWS * MDIM];     // 4 MB
__device__ __align__(256) float g_h     [NROWS * HDIM];     // 16 MB (tf32-rounded)
__device__ __align__(256) float g_feats2[NROWS * MDIM];     // 4 MB (tf32-rounded)
__device__ __align__(256) float g_wmapT [VDIM * MDIM];      // 1 MB (tf32-rounded)
__device__ __align__(256) float g_w2r   [MDIM * MDIM * HDIM]; // 64 MB (tf32 W2)
__device__ __align__(256) float g_w1r   [4 * MDIM * MDIM];  // 256 KB (tf32 W1)
__device__ __align__(256) float g_xhi   [NROWS * VDIM];     // 64 MB (x hi part)
__device__ __align__(256) float g_xlo   [NROWS * VDIM];     // 64 MB (x lo part)
__device__ __align__(256) float g_wmh   [MDIM * VDIM];      // 1 MB (Wmap hi)
__device__ __align__(256) float g_wml   [MDIM * VDIM];      // 1 MB (Wmap lo)

// ---------------- common PTX helpers ----------------
__device__ __forceinline__ uint32_t smem_u32(const void* p) {
    uint32_t a;
    asm("{ .reg .u64 t; cvta.to.shared.u64 t, %1; cvt.u32.u64 %0, t; }"
        : "=r"(a) : "l"(p));
    return a;
}
__device__ __forceinline__ void cp_async16(uint32_t dst, const void* src) {
    asm volatile("cp.async.cg.shared.global [%0], [%1], 16;"
                 :: "r"(dst), "l"(src));
}
__device__ __forceinline__ void cp_commit() {
    asm volatile("cp.async.commit_group;" ::: "memory");
}
template <int N>
__device__ __forceinline__ void cp_wait() {
    asm volatile("cp.async.wait_group %0;" :: "n"(N) : "memory");
}
__device__ __forceinline__ uint32_t f2tf32(float f) {
    uint32_t r;
    asm("cvt.rna.tf32.f32 %0, %1;" : "=r"(r) : "f"(f));
    return r;
}
__device__ __forceinline__ void mma_tf32(float* d, const uint32_t* a,
                                         const uint32_t* b) {
    asm volatile(
        "mma.sync.aligned.m16n8k8.row.col.f32.tf32.tf32.f32 "
        "{%0,%1,%2,%3}, {%4,%5,%6,%7}, {%8,%9}, {%0,%1,%2,%3};"
        : "+f"(d[0]), "+f"(d[1]), "+f"(d[2]), "+f"(d[3])
        : "r"(a[0]), "r"(a[1]), "r"(a[2]), "r"(a[3]), "r"(b[0]), "r"(b[1]));
}
__device__ __forceinline__ void ldsm_x4(uint32_t& r0, uint32_t& r1,
                                        uint32_t& r2, uint32_t& r3,
                                        uint32_t addr) {
    asm volatile("ldmatrix.sync.aligned.m8n8.x4.shared.b16 {%0,%1,%2,%3}, [%4];"
                 : "=r"(r0), "=r"(r1), "=r"(r2), "=r"(r3) : "r"(addr));
}

// =======================================================================
// Pre-round a buffer to tf32 format
// =======================================================================
__global__ __launch_bounds__(256)
void round_tf32_kernel(const float4* __restrict__ in, float4* __restrict__ out,
                       int n4)
{
    int i = blockIdx.x * blockDim.x + threadIdx.x;
    int stride = gridDim.x * blockDim.x;
    for (; i < n4; i += stride) {
        float4 v = in[i];
        float4 o;
        o.x = __uint_as_float(f2tf32(v.x));
        o.y = __uint_as_float(f2tf32(v.y));
        o.z = __uint_as_float(f2tf32(v.z));
        o.w = __uint_as_float(f2tf32(v.w));
        out[i] = o;
    }
}

// =======================================================================
// 3xTF32 split: hi = rnd(v), lo = rnd(v - hi)
// =======================================================================
__global__ __launch_bounds__(256)
void split_tf32_kernel(const float4* __restrict__ in,
                       float4* __restrict__ hi, float4* __restrict__ lo,
                       int n4)
{
    int i = blockIdx.x * blockDim.x + threadIdx.x;
    int stride = gridDim.x * blockDim.x;
    for (; i < n4; i += stride) {
        float4 v = in[i];
        float4 h4, l4;
        h4.x = __uint_as_float(f2tf32(v.x)); l4.x = __uint_as_float(f2tf32(v.x - h4.x));
        h4.y = __uint_as_float(f2tf32(v.y)); l4.y = __uint_as_float(f2tf32(v.y - h4.y));
        h4.z = __uint_as_float(f2tf32(v.z)); l4.z = __uint_as_float(f2tf32(v.z - h4.z));
        h4.w = __uint_as_float(f2tf32(v.w)); l4.w = __uint_as_float(f2tf32(v.w - h4.w));
        hi[i] = h4;
        lo[i] = l4;
    }
}

// =======================================================================
// W_map transpose (+ tf32 round): WT[v][i] = round(W[i][v])
// =======================================================================
__global__ __launch_bounds__(256)
void transpose_wmap(const float* __restrict__ W, float* __restrict__ WT)
{
    __shared__ float t[32][33];
    const int bx = blockIdx.x * 32;   // v
    const int by = blockIdx.y * 32;   // i
    const int tx = threadIdx.x & 31;
    const int ty = threadIdx.x >> 5;  // 0..7
#pragma unroll
    for (int r = 0; r < 32; r += 8)
        t[ty + r][tx] = W[(size_t)(by + ty + r) * VDIM + bx + tx];
    __syncthreads();
#pragma unroll
    for (int r = 0; r < 32; r += 8)
        WT[(size_t)(bx + ty + r) * MDIM + by + tx] =
            __uint_as_float(f2tf32(t[tx][ty + r]));
}

// =======================================================================
// Step 1 via 3xTF32: feats = x @ Wmap^T with fp32-grade accuracy.
//   acc = xhi.whi + xhi.wlo + xlo.whi   (xlo.wlo ~ 2^-21, dropped)
// M-tile 64, N=128 (full), K=2048, KC=64, 2-stage cp.async ring, ldmatrix.
// Stage rows: Ahi[0,64) Alo[64,128) Bhi[128,256) Blo[256,384), stride 68.
// =======================================================================
#define G3_KC    64
#define G3_NCH   (VDIM / G3_KC)            // 32
#define G3_STR   68
#define G3_STAGE (384 * G3_STR)            // 26112 floats
#define G3_SMEM  (2 * G3_STAGE * 4)        // 208896 B

__global__ __launch_bounds__(256, 1)
void gemm_3xtf32(const float* __restrict__ xhi, const float* __restrict__ xlo,
                 const float* __restrict__ wmh, const float* __restrict__ wml,
                 float* __restrict__ C)
{
    extern __shared__ float smf[];
    const uint32_t s_u = smem_u32(smf);

    const int tid  = threadIdx.x;
    const int wid  = tid >> 5;
    const int lane = tid & 31;
    const int wr   = wid >> 2;         // 0..1 -> rows 32*wr
    const int wc   = wid & 3;          // 0..3 -> cols 32*wc
    const int qr   = lane >> 2;
    const int qc   = lane & 3;
    const int m0   = blockIdx.x * 64;

    const int lt = lane >> 3;
    const int lr = lane & 7;
    // A frag ldsm offsets (rows relative to region base)
    const int a_off = (wr * 32 + (lt & 1) * 8 + lr) * G3_STR + (lt >> 1) * 4;
    // B frag ldsm offsets
    const int b_off = (wc * 32 + (lt >> 1) * 8 + lr) * G3_STR + (lt & 1) * 4;

    float acc[2][4][4];
#pragma unroll
    for (int mt = 0; mt < 2; mt++)
#pragma unroll
        for (int nt = 0; nt < 4; nt++)
#pragma unroll
            for (int v = 0; v < 4; v++) acc[mt][nt][v] = 0.f;

    auto load_chunk = [&](int c) {
        const int s = c & 1;
        const int kc = c * G3_KC;
        const uint32_t base = s_u + s * G3_STAGE * 4;
#pragma unroll
        for (int o = 0; o < 4; o++) {       // A hi: 64 rows x 16 granules
            int li = o * 256 + tid;
            int row = li >> 4, g = li & 15;
            cp_async16(base + (row * G3_STR + g * 4) * 4,
                       xhi + (size_t)(m0 + row) * VDIM + kc + g * 4);
        }
#pragma unroll
        for (int o = 0; o < 4; o++) {       // A lo
            int li = o * 256 + tid;
            int row = li >> 4, g = li & 15;
            cp_async16(base + ((64 + row) * G3_STR + g * 4) * 4,
                       xlo + (size_t)(m0 + row) * VDIM + kc + g * 4);
        }
#pragma unroll
        for (int o = 0; o < 8; o++) {       // B hi: 128 rows x 16 granules
            int li = o * 256 + tid;
            int row = li >> 4, g = li & 15;
            cp_async16(base + ((128 + row) * G3_STR + g * 4) * 4,
                       wmh + (size_t)row * VDIM + kc + g * 4);
        }
#pragma unroll
        for (int o = 0; o < 8; o++) {       // B lo
            int li = o * 256 + tid;
            int row = li >> 4, g = li & 15;
            cp_async16(base + ((256 + row) * G3_STR + g * 4) * 4,
                       wml + (size_t)row * VDIM + kc + g * 4);
        }
        cp_commit();
    };

    load_chunk(0);

    for (int c = 0; c < G3_NCH; c++) {
        cp_wait<0>();
        __syncthreads();
        if (c + 1 < G3_NCH) load_chunk(c + 1);

        const uint32_t base = s_u + (c & 1) * G3_STAGE * 4;
        const uint32_t aho = base + (uint32_t)a_off * 4;
        const uint32_t alo_ = aho + 64u * G3_STR * 4;
        const uint32_t bho = base + 128u * G3_STR * 4 + (uint32_t)b_off * 4;
        const uint32_t blo_ = bho + 128u * G3_STR * 4;

#pragma unroll
        for (int k8 = 0; k8 < 8; k8++) {
            const int k0 = k8 * 8;
            uint32_t ah[2][4], al[2][4], bh[4][2], bl[4][2];
#pragma unroll
            for (int mt = 0; mt < 2; mt++) {
                ldsm_x4(ah[mt][0], ah[mt][1], ah[mt][2], ah[mt][3],
                        aho + (uint32_t)(mt * 16 * G3_STR + k0) * 4);
                ldsm_x4(al[mt][0], al[mt][1], al[mt][2], al[mt][3],
                        alo_ + (uint32_t)(mt * 16 * G3_STR + k0) * 4);
            }
#pragma unroll
            for (int p = 0; p < 2; p++) {
                uint32_t r0, r1, r2, r3;
                ldsm_x4(r0, r1, r2, r3,
                        bho + (uint32_t)(p * 16 * G3_STR + k0) * 4);
                bh[2 * p][0] = r0;  bh[2 * p][1] = r1;
                bh[2 * p + 1][0] = r2;  bh[2 * p + 1][1] = r3;
                ldsm_x4(r0, r1, r2, r3,
                        blo_ + (uint32_t)(p * 16 * G3_STR + k0) * 4);
                bl[2 * p][0] = r0;  bl[2 * p][1] = r1;
                bl[2 * p + 1][0] = r2;  bl[2 * p + 1][1] = r3;
            }
#pragma unroll
            for (int mt = 0; mt < 2; mt++)
#pragma unroll
                for (int nt = 0; nt < 4; nt++) {
                    mma_tf32(acc[mt][nt], ah[mt], bh[nt]);
                    mma_tf32(acc[mt][nt], ah[mt], bl[nt]);
                    mma_tf32(acc[mt][nt], al[mt], bh[nt]);
                }
        }
    }

    // epilogue: direct fp32 stores to feats [8192][128]
#pragma unroll
    for (int mt = 0; mt < 2; mt++) {
#pragma unroll
        for (int nt = 0; nt < 4; nt++) {
            int col = wc * 32 + nt * 8 + 2 * qc;
#pragma unroll
            for (int h2 = 0; h2 < 2; h2++) {
                int row = m0 + wr * 32 + mt * 16 + qr + 8 * h2;
                float2 o = make_float2(acc[mt][nt][2 * h2],
                                       acc[mt][nt][2 * h2 + 1]);
                *(float2*)(C + (size_t)row * MDIM + col) = o;
            }
        }
    }
}

// =======================================================================
// One-shot tf32 GEMM for K=128 (steps 2 & 5): C = epi(A[M,128] @ B[N,128]^T)
// B via ldmatrix (pre-rounded). A: CVTA -> scalar LDS + cvt; else ldmatrix.
// =======================================================================
#define EPI_SILU 1
#define EPI_RES  2
#define GT_SMEM  (2 * 128 * 132 * 4)    // 135168 B

template <int EPI, bool CVTA>
__global__ __launch_bounds__(256, 1)
void gemm_tf32_k128(const float* __restrict__ A, const float* __restrict__ B,
                    const float* __restrict__ bias, const float* __restrict__ X,
                    float* __restrict__ C, int N)
{
    extern __shared__ float sm[];
    float* sA = sm;                 // [128][132]
    float* sB = sm + 128 * 132;     // [128][132]
    const uint32_t sA_u = smem_u32(sA);
    const uint32_t sB_u = smem_u32(sB);

    const int tid  = threadIdx.x;
    const int wid  = tid >> 5;
    const int lane = tid & 31;
    const int wr   = wid >> 2;
    const int wc   = wid & 3;
    const int qr   = lane >> 2;
    const int qc   = lane & 3;
    const int m0   = blockIdx.x * 128;
    const int n0   = blockIdx.y * 128;

    const int lt = lane >> 3;
    const int lr = lane & 7;
    const int a_off = (wr * 64 + (lt & 1) * 8 + lr) * 132 + (lt >> 1) * 4;
    const int b_off = (wc * 32 + (lt >> 1) * 8 + lr) * 132 + (lt & 1) * 4;

#pragma unroll
    for (int o = 0; o < 16; o++) {
        int li = o * 256 + tid;
        int row = li >> 5, g = li & 31;
        cp_async16(sA_u + (row * 132 + g * 4) * 4,
                   A + (size_t)(m0 + row) * MDIM + g * 4);
    }
#pragma unroll
    for (int o = 0; o < 16; o++) {
        int li = o * 256 + tid;
        int row = li >> 5, g = li & 31;
        cp_async16(sB_u + (row * 132 + g * 4) * 4,
                   B + (size_t)(n0 + row) * MDIM + g * 4);
    }
    cp_commit();

    float acc[4][4][4];
#pragma unroll
    for (int mt = 0; mt < 4; mt++)
#pragma unroll
        for (int nt = 0; nt < 4; nt++)
#pragma unroll
            for (int v = 0; v < 4; v++) acc[mt][nt][v] = 0.f;

    cp_wait<0>();
    __syncthreads();

#pragma unroll
    for (int k8 = 0; k8 < 16; k8++) {
        const int k0 = k8 * 8;
        uint32_t af[4][4], bf[4][2];
        if (CVTA) {
#pragma unroll
            for (int mt = 0; mt < 4; mt++) {
                const float* ar = sA + (wr * 64 + mt * 16 + qr) * 132 + k0 + qc;
                af[mt][0] = f2tf32(ar[0]);
                af[mt][1] = f2tf32(ar[8 * 132]);
                af[mt][2] = f2tf32(ar[4]);
                af[mt][3] = f2tf32(ar[8 * 132 + 4]);
            }
        } else {
#pragma unroll
            for (int mt = 0; mt < 4; mt++)
                ldsm_x4(af[mt][0], af[mt][1], af[mt][2], af[mt][3],
                        sA_u + (uint32_t)(a_off + mt * 16 * 132 + k0) * 4);
        }
#pragma unroll
        for (int p = 0; p < 2; p++) {
            uint32_t r0, r1, r2, r3;
            ldsm_x4(r0, r1, r2, r3,
                    sB_u + (uint32_t)(b_off + p * 16 * 132 + k0) * 4);
            bf[2 * p][0] = r0;  bf[2 * p][1] = r1;
            bf[2 * p + 1][0] = r2;  bf[2 * p + 1][1] = r3;
        }
#pragma unroll
        for (int mt = 0; mt < 4; mt++)
#pragma unroll
            for (int nt = 0; nt < 4; nt++)
                mma_tf32(acc[mt][nt], af[mt], bf[nt]);
    }

#pragma unroll
    for (int mt = 0; mt < 4; mt++) {
#pragma unroll
        for (int nt = 0; nt < 4; nt++) {
            int col = n0 + wc * 32 + nt * 8 + 2 * qc;
#pragma unroll
            for (int h2 = 0; h2 < 2; h2++) {
                int row = m0 + wr * 64 + mt * 16 + qr + 8 * h2;
                float v0 = acc[mt][nt][2 * h2];
                float v1 = acc[mt][nt][2 * h2 + 1];
                size_t base = (size_t)row * N + col;
                float2 o;
                if (EPI == EPI_SILU) {
                    float z0 = v0 + bias[col];
                    float z1 = v1 + bias[col + 1];
                    o.x = __uint_as_float(f2tf32(z0 / (1.f + expf(-z0))));
                    o.y = __uint_as_float(f2tf32(z1 / (1.f + expf(-z1))));
                } else {
                    float2 xv = *(const float2*)(X + base);
                    o.x = v0 + xv.x;
                    o.y = v1 + xv.y;
                }
                *(float2*)(C + base) = o;
            }
        }
    }
}

// =======================================================================
// K3 (tf32 mma.sync + ldmatrix; operands pre-rounded in gmem) — as R9.
// =======================================================================
#define K3_BM   128
#define K3_BN   256
#define K3_KC   64
#define K3_NCH  8
#define K3_STR  68
#define K3_ASTG (K3_BM * K3_STR)
#define K3_BSTG (K3_BN * K3_STR)
#define K3_SMEM_BYTES (2 * (K3_ASTG + K3_BSTG) * 4 + 2048)   // 210944 B

__global__ __launch_bounds__(256, 1)
void k3_mma(const float* __restrict__ W2r,
            const float* __restrict__ feats,
            const float* __restrict__ h,
            const float* __restrict__ b2,
            float* __restrict__ feats2)
{
    extern __shared__ float smf[];
    float* sAf  = smf;
    float* sBf  = smf + 2 * K3_ASTG;
    float* sRed = smf + 2 * (K3_ASTG + K3_BSTG);
    const uint32_t sA_u = smem_u32(sAf);
    const uint32_t sB_u = smem_u32(sBf);

    const int tid  = threadIdx.x;
    const int wid  = tid >> 5;
    const int lane = tid & 31;
    const int wr   = wid >> 2;
    const int wc   = wid & 3;
    const int qr   = lane >> 2;
    const int qc   = lane & 3;
    const int m0   = blockIdx.x * K3_BM;
    const int nb   = blockIdx.y;

    const int lt = lane >> 3;
    const int lr = lane & 7;
    const int a_off = (wr * 64 + (lt & 1) * 8 + lr) * K3_STR + (lt >> 1) * 4;
    const int b_off = (wc * 64 + (lt >> 1) * 8 + lr) * K3_STR + (lt & 1) * 4;

    float acc[4][8][4];
#pragma unroll
    for (int mt = 0; mt < 4; mt++)
#pragma unroll
        for (int nt = 0; nt < 8; nt++)
#pragma unroll
            for (int v = 0; v < 4; v++) acc[mt][nt][v] = 0.f;

    auto load_chunk = [&](int c) {
        const int s = c & 1;
        const int kc = c * K3_KC;
        const uint32_t ab = sA_u + s * K3_ASTG * 4;
        const uint32_t bb = sB_u + s * K3_BSTG * 4;
#pragma unroll
        for (int o = 0; o < 8; o++) {
            int li = o * 256 + tid;
            int row = li >> 4, g = li & 15;
            cp_async16(ab + (row * K3_STR + g * 4) * 4,
                       h + (size_t)(m0 + row) * HDIM + kc + g * 4);
        }
#pragma unroll
        for (int o = 0; o < 16; o++) {
            int li = o * 256 + tid;
            int row = li >> 4, g = li & 15;
            cp_async16(bb + (row * K3_STR + g * 4) * 4,
                       W2r + (size_t)(nb * K3_BN + row) * HDIM + kc + g * 4);
        }
        cp_commit();
    };

    load_chunk(0);

    for (int c = 0; c < K3_NCH; c++) {
        cp_wait<0>();
        __syncthreads();
        if (c + 1 < K3_NCH) load_chunk(c + 1);

        const uint32_t ab = sA_u + (c & 1) * K3_ASTG * 4;
        const uint32_t bb = sB_u + (c & 1) * K3_BSTG * 4;

#pragma unroll
        for (int k8 = 0; k8 < 8; k8++) {
            const int k0 = k8 * 8;
            uint32_t af[4][4], bf[8][2];
#pragma unroll
            for (int mt = 0; mt < 4; mt++)
                ldsm_x4(af[mt][0], af[mt][1], af[mt][2], af[mt][3],
                        ab + (uint32_t)(a_off + mt * 16 * K3_STR + k0) * 4);
#pragma unroll
            for (int p = 0; p < 4; p++) {
                uint32_t r0, r1, r2, r3;
                ldsm_x4(r0, r1, r2, r3,
                        bb + (uint32_t)(b_off + p * 16 * K3_STR + k0) * 4);
                bf[2 * p][0] = r0;  bf[2 * p][1] = r1;
                bf[2 * p + 1][0] = r2;  bf[2 * p + 1][1] = r3;
            }
#pragma unroll
            for (int mt = 0; mt < 4; mt++)
#pragma unroll
                for (int nt = 0; nt < 8; nt++)
                    mma_tf32(acc[mt][nt], af[mt], bf[nt]);
        }
    }
    __syncthreads();

    // ---- epilogue: stage feats [128][132], reduce over j ----
    float* fs = sAf;
#pragma unroll
    for (int o = 0; o < 16; o++) {
        int li = o * 256 + tid;
        int row = li >> 5, g = li & 31;
        float4 v = *(const float4*)(feats + (size_t)(m0 + row) * MDIM + g * 4);
        float* d = fs + row * 132 + g * 4;
        d[0] = v.x; d[1] = v.y; d[2] = v.z; d[3] = v.w;
    }
    __syncthreads();

#pragma unroll
    for (int mt = 0; mt < 4; mt++) {
#pragma unroll
        for (int h2 = 0; h2 < 2; h2++) {
            int rl = wr * 64 + mt * 16 + qr + 8 * h2;
            float p = 0.f;
#pragma unroll
            for (int nt = 0; nt < 8; nt++) {
                int j0 = (wc & 1) * 64 + nt * 8 + 2 * qc;
                p = fmaf(acc[mt][nt][2 * h2],     fs[rl * 132 + j0],     p);
                p = fmaf(acc[mt][nt][2 * h2 + 1], fs[rl * 132 + j0 + 1], p);
            }
            p += __shfl_xor_sync(0xffffffffu, p, 1);
            p += __shfl_xor_sync(0xffffffffu, p, 2);
            if (qc == 0) sRed[rl * 4 + wc] = p;
        }
    }
    __syncthreads();

    {
        int row = tid >> 1, iv = tid & 1;
        float s = sRed[row * 4 + iv * 2] + sRed[row * 4 + iv * 2 + 1];
        const float4* bb2 = (const float4*)(b2 + (size_t)(nb * 2 + iv) * MDIM);
        const float* fr = fs + row * 132;
        float bacc = 0.f;
#pragma unroll
        for (int j = 0; j < 32; j++) {
            float4 v = bb2[j];
            bacc = fmaf(v.x, fr[4 * j + 0],
                   fmaf(v.y, fr[4 * j + 1],
                   fmaf(v.z, fr[4 * j + 2],
                   fmaf(v.w, fr[4 * j + 3], bacc))));
        }
        feats2[(size_t)(m0 + row) * MDIM + nb * 2 + iv] =
            __uint_as_float(f2tf32(s + bacc));
    }
}

// =======================================================================
// Host launcher
// =======================================================================
extern "C" void kernel_launch(void* const* d_in, const int* in_sizes, int n_in,
                              void* d_out, int out_size)
{
    const float* x    = (const float*)d_in[0];
    const float* Wmap = (const float*)d_in[1];
    const float* W1   = (const float*)d_in[2];
    const float* b1   = (const float*)d_in[3];
    const float* W2   = (const float*)d_in[4];
    const float* b2   = (const float*)d_in[5];
    float* out = (float*)d_out;

    void *pf, *ph, *pf2, *pwt, *pw2, *pw1, *pxh, *pxl, *pwh, *pwl;
    cudaGetSymbolAddress(&pf,  g_feats);
    cudaGetSymbolAddress(&ph,  g_h);
    cudaGetSymbolAddress(&pf2, g_feats2);
    cudaGetSymbolAddress(&pwt, g_wmapT);
    cudaGetSymbolAddress(&pw2, g_w2r);
    cudaGetSymbolAddress(&pw1, g_w1r);
    cudaGetSymbolAddress(&pxh, g_xhi);
    cudaGetSymbolAddress(&pxl, g_xlo);
    cudaGetSymbolAddress(&pwh, g_wmh);
    cudaGetSymbolAddress(&pwl, g_wml);
    float* feats  = (float*)pf;
    float* hbuf   = (float*)ph;
    float* feats2 = (float*)pf2;
    float* wmapT  = (float*)pwt;
    float* w2r    = (float*)pw2;
    float* w1r    = (float*)pw1;
    float* xhi    = (float*)pxh;
    float* xlo    = (float*)pxl;
    float* wmh    = (float*)pwh;
    float* wml    = (float*)pwl;

    cudaFuncSetAttribute(k3_mma, cudaFuncAttributeMaxDynamicSharedMemorySize,
                         K3_SMEM_BYTES);
    cudaFuncSetAttribute(gemm_3xtf32,
                         cudaFuncAttributeMaxDynamicSharedMemorySize, G3_SMEM);
    cudaFuncSetAttribute(gemm_tf32_k128<EPI_SILU, true>,
                         cudaFuncAttributeMaxDynamicSharedMemorySize, GT_SMEM);
    cudaFuncSetAttribute(gemm_tf32_k128<EPI_RES, false>,
                         cudaFuncAttributeMaxDynamicSharedMemorySize, GT_SMEM);

    dim3 blk(256);

    // 0a) pre-round W2, W1; split x and Wmap into tf32 hi/lo
    round_tf32_kernel<<<2048, blk>>>((const float4*)W2, (float4*)w2r,
                                     MDIM * MDIM * HDIM / 4);
    round_tf32_kernel<<<64, blk>>>((const float4*)W1, (float4*)w1r,
                                   4 * MDIM * MDIM / 4);
    split_tf32_kernel<<<2048, blk>>>((const float4*)x, (float4*)xhi,
                                     (float4*)xlo, NROWS * VDIM / 4);
    split_tf32_kernel<<<64, blk>>>((const float4*)Wmap, (float4*)wmh,
                                   (float4*)wml, MDIM * VDIM / 4);
    // 0b) WmapT = round(W_map^T)
    transpose_wmap<<<dim3(VDIM / 32, MDIM / 32), blk>>>(Wmap, wmapT);

    // 1) feats = x @ W_map^T  via 3xTF32  (fp32-grade accuracy)
    gemm_3xtf32<<<NROWS / 64, blk, G3_SMEM>>>(xhi, xlo, wmh, wml, feats);

    // 2) h = round(silu(feats @ W1^T + b1))  (tf32)
    gemm_tf32_k128<EPI_SILU, true><<<dim3(NROWS / 128, HDIM / 128), blk, GT_SMEM>>>(
        feats, w1r, b1, nullptr, hbuf, HDIM);

    // 3+4) feats2 = round(((h @ W2r^T) + b2-term) . feats)
    k3_mma<<<dim3(NROWS / K3_BM, 16384 / K3_BN), blk, K3_SMEM_BYTES>>>(
        w2r, feats, hbuf, b2, feats2);

    // 5) out = x + feats2 @ wmapT^T   (tf32, ldmatrix both operands)
    gemm_tf32_k128<EPI_RES, false><<<dim3(NROWS / 128, VDIM / 128), blk, GT_SMEM>>>(
        feats2, wmapT, nullptr, x, out, VDIM);
}

// round 13
// speedup vs baseline: 4.9681x; 1.0438x over previous
#include <cuda_runtime.h>
#include <cstdint>
#include <cstdio>

// Problem dims (fixed)
#define NROWS 8192
#define VDIM  2048
#define MDIM  128
#define HDIM  512

// Scratch (allocation-free rule: __device__ globals)
__device__ __align__(256) float g_feats [NROWS * MDIM];     // 4 MB
__device__ __align__(256) float g_h     [NROWS * HDIM];     // 16 MB (tf32-rounded)
__device__ __align__(256) float g_feats2[NROWS * MDIM];     // 4 MB (tf32-rounded)
__device__ __align__(256) float g_wmapT [VDIM * MDIM];      // 1 MB (tf32-rounded)
__device__ __align__(256) float g_w2r   [MDIM * MDIM * HDIM]; // 64 MB (tf32 W2)
__device__ __align__(256) float g_w1r   [4 * MDIM * MDIM];  // 256 KB (tf32 W1)
__device__ __align__(256) float g_xhi   [NROWS * VDIM];     // 64 MB (x hi part)
__device__ __align__(256) float g_xlo   [NROWS * VDIM];     // 64 MB (x lo part)
__device__ __align__(256) float g_wmh   [MDIM * VDIM];      // 1 MB (Wmap hi)
__device__ __align__(256) float g_wml   [MDIM * VDIM];      // 1 MB (Wmap lo)

// ---------------- common PTX helpers ----------------
__device__ __forceinline__ uint32_t smem_u32(const void* p) {
    uint32_t a;
    asm("{ .reg .u64 t; cvta.to.shared.u64 t, %1; cvt.u32.u64 %0, t; }"
        : "=r"(a) : "l"(p));
    return a;
}
__device__ __forceinline__ void cp_async16(uint32_t dst, const void* src) {
    asm volatile("cp.async.cg.shared.global [%0], [%1], 16;"
                 :: "r"(dst), "l"(src));
}
__device__ __forceinline__ void cp_commit() {
    asm volatile("cp.async.commit_group;" ::: "memory");
}
template <int N>
__device__ __forceinline__ void cp_wait() {
    asm volatile("cp.async.wait_group %0;" :: "n"(N) : "memory");
}
__device__ __forceinline__ uint32_t f2tf32(float f) {
    uint32_t r;
    asm("cvt.rna.tf32.f32 %0, %1;" : "=r"(r) : "f"(f));
    return r;
}
__device__ __forceinline__ void mma_tf32(float* d, const uint32_t* a,
                                         const uint32_t* b) {
    asm volatile(
        "mma.sync.aligned.m16n8k8.row.col.f32.tf32.tf32.f32 "
        "{%0,%1,%2,%3}, {%4,%5,%6,%7}, {%8,%9}, {%0,%1,%2,%3};"
        : "+f"(d[0]), "+f"(d[1]), "+f"(d[2]), "+f"(d[3])
        : "r"(a[0]), "r"(a[1]), "r"(a[2]), "r"(a[3]), "r"(b[0]), "r"(b[1]));
}
__device__ __forceinline__ void ldsm_x4(uint32_t& r0, uint32_t& r1,
                                        uint32_t& r2, uint32_t& r3,
                                        uint32_t addr) {
    asm volatile("ldmatrix.sync.aligned.m8n8.x4.shared.b16 {%0,%1,%2,%3}, [%4];"
                 : "=r"(r0), "=r"(r1), "=r"(r2), "=r"(r3) : "r"(addr));
}

// =======================================================================
// Pre-round a buffer to tf32 format
// =======================================================================
__global__ __launch_bounds__(256)
void round_tf32_kernel(const float4* __restrict__ in, float4* __restrict__ out,
                       int n4)
{
    int i = blockIdx.x * blockDim.x + threadIdx.x;
    int stride = gridDim.x * blockDim.x;
    for (; i < n4; i += stride) {
        float4 v = in[i];
        float4 o;
        o.x = __uint_as_float(f2tf32(v.x));
        o.y = __uint_as_float(f2tf32(v.y));
        o.z = __uint_as_float(f2tf32(v.z));
        o.w = __uint_as_float(f2tf32(v.w));
        out[i] = o;
    }
}

// =======================================================================
// 3xTF32 split: hi = rnd(v), lo = rnd(v - hi)
// =======================================================================
__global__ __launch_bounds__(256)
void split_tf32_kernel(const float4* __restrict__ in,
                       float4* __restrict__ hi, float4* __restrict__ lo,
                       int n4)
{
    int i = blockIdx.x * blockDim.x + threadIdx.x;
    int stride = gridDim.x * blockDim.x;
    for (; i < n4; i += stride) {
        float4 v = in[i];
        float4 h4, l4;
        h4.x = __uint_as_float(f2tf32(v.x)); l4.x = __uint_as_float(f2tf32(v.x - h4.x));
        h4.y = __uint_as_float(f2tf32(v.y)); l4.y = __uint_as_float(f2tf32(v.y - h4.y));
        h4.z = __uint_as_float(f2tf32(v.z)); l4.z = __uint_as_float(f2tf32(v.z - h4.z));
        h4.w = __uint_as_float(f2tf32(v.w)); l4.w = __uint_as_float(f2tf32(v.w - h4.w));
        hi[i] = h4;
        lo[i] = l4;
    }
}

// =======================================================================
// W_map transpose (+ tf32 round): WT[v][i] = round(W[i][v])
// =======================================================================
__global__ __launch_bounds__(256)
void transpose_wmap(const float* __restrict__ W, float* __restrict__ WT)
{
    __shared__ float t[32][33];
    const int bx = blockIdx.x * 32;   // v
    const int by = blockIdx.y * 32;   // i
    const int tx = threadIdx.x & 31;
    const int ty = threadIdx.x >> 5;  // 0..7
#pragma unroll
    for (int r = 0; r < 32; r += 8)
        t[ty + r][tx] = W[(size_t)(by + ty + r) * VDIM + bx + tx];
    __syncthreads();
#pragma unroll
    for (int r = 0; r < 32; r += 8)
        WT[(size_t)(bx + ty + r) * MDIM + by + tx] =
            __uint_as_float(f2tf32(t[tx][ty + r]));
}

// =======================================================================
// Step 1 via 3xTF32: feats = x @ Wmap^T with fp32-grade accuracy.
// (unchanged from R10)
// =======================================================================
#define G3_KC    64
#define G3_NCH   (VDIM / G3_KC)            // 32
#define G3_STR   68
#define G3_STAGE (384 * G3_STR)            // 26112 floats
#define G3_SMEM  (2 * G3_STAGE * 4)        // 208896 B

__global__ __launch_bounds__(256, 1)
void gemm_3xtf32(const float* __restrict__ xhi, const float* __restrict__ xlo,
                 const float* __restrict__ wmh, const float* __restrict__ wml,
                 float* __restrict__ C)
{
    extern __shared__ float smf[];
    const uint32_t s_u = smem_u32(smf);

    const int tid  = threadIdx.x;
    const int wid  = tid >> 5;
    const int lane = tid & 31;
    const int wr   = wid >> 2;
    const int wc   = wid & 3;
    const int qr   = lane >> 2;
    const int qc   = lane & 3;
    const int m0   = blockIdx.x * 64;

    const int lt = lane >> 3;
    const int lr = lane & 7;
    const int a_off = (wr * 32 + (lt & 1) * 8 + lr) * G3_STR + (lt >> 1) * 4;
    const int b_off = (wc * 32 + (lt >> 1) * 8 + lr) * G3_STR + (lt & 1) * 4;

    float acc[2][4][4];
#pragma unroll
    for (int mt = 0; mt < 2; mt++)
#pragma unroll
        for (int nt = 0; nt < 4; nt++)
#pragma unroll
            for (int v = 0; v < 4; v++) acc[mt][nt][v] = 0.f;

    auto load_chunk = [&](int c) {
        const int s = c & 1;
        const int kc = c * G3_KC;
        const uint32_t base = s_u + s * G3_STAGE * 4;
#pragma unroll
        for (int o = 0; o < 4; o++) {
            int li = o * 256 + tid;
            int row = li >> 4, g = li & 15;
            cp_async16(base + (row * G3_STR + g * 4) * 4,
                       xhi + (size_t)(m0 + row) * VDIM + kc + g * 4);
        }
#pragma unroll
        for (int o = 0; o < 4; o++) {
            int li = o * 256 + tid;
            int row = li >> 4, g = li & 15;
            cp_async16(base + ((64 + row) * G3_STR + g * 4) * 4,
                       xlo + (size_t)(m0 + row) * VDIM + kc + g * 4);
        }
#pragma unroll
        for (int o = 0; o < 8; o++) {
            int li = o * 256 + tid;
            int row = li >> 4, g = li & 15;
            cp_async16(base + ((128 + row) * G3_STR + g * 4) * 4,
                       wmh + (size_t)row * VDIM + kc + g * 4);
        }
#pragma unroll
        for (int o = 0; o < 8; o++) {
            int li = o * 256 + tid;
            int row = li >> 4, g = li & 15;
            cp_async16(base + ((256 + row) * G3_STR + g * 4) * 4,
                       wml + (size_t)row * VDIM + kc + g * 4);
        }
        cp_commit();
    };

    load_chunk(0);

    for (int c = 0; c < G3_NCH; c++) {
        cp_wait<0>();
        __syncthreads();
        if (c + 1 < G3_NCH) load_chunk(c + 1);

        const uint32_t base = s_u + (c & 1) * G3_STAGE * 4;
        const uint32_t aho = base + (uint32_t)a_off * 4;
        const uint32_t alo_ = aho + 64u * G3_STR * 4;
        const uint32_t bho = base + 128u * G3_STR * 4 + (uint32_t)b_off * 4;
        const uint32_t blo_ = bho + 128u * G3_STR * 4;

#pragma unroll
        for (int k8 = 0; k8 < 8; k8++) {
            const int k0 = k8 * 8;
            uint32_t ah[2][4], al[2][4], bh[4][2], bl[4][2];
#pragma unroll
            for (int mt = 0; mt < 2; mt++) {
                ldsm_x4(ah[mt][0], ah[mt][1], ah[mt][2], ah[mt][3],
                        aho + (uint32_t)(mt * 16 * G3_STR + k0) * 4);
                ldsm_x4(al[mt][0], al[mt][1], al[mt][2], al[mt][3],
                        alo_ + (uint32_t)(mt * 16 * G3_STR + k0) * 4);
            }
#pragma unroll
            for (int p = 0; p < 2; p++) {
                uint32_t r0, r1, r2, r3;
                ldsm_x4(r0, r1, r2, r3,
                        bho + (uint32_t)(p * 16 * G3_STR + k0) * 4);
                bh[2 * p][0] = r0;  bh[2 * p][1] = r1;
                bh[2 * p + 1][0] = r2;  bh[2 * p + 1][1] = r3;
                ldsm_x4(r0, r1, r2, r3,
                        blo_ + (uint32_t)(p * 16 * G3_STR + k0) * 4);
                bl[2 * p][0] = r0;  bl[2 * p][1] = r1;
                bl[2 * p + 1][0] = r2;  bl[2 * p + 1][1] = r3;
            }
#pragma unroll
            for (int mt = 0; mt < 2; mt++)
#pragma unroll
                for (int nt = 0; nt < 4; nt++) {
                    mma_tf32(acc[mt][nt], ah[mt], bh[nt]);
                    mma_tf32(acc[mt][nt], ah[mt], bl[nt]);
                    mma_tf32(acc[mt][nt], al[mt], bh[nt]);
                }
        }
    }

#pragma unroll
    for (int mt = 0; mt < 2; mt++) {
#pragma unroll
        for (int nt = 0; nt < 4; nt++) {
            int col = wc * 32 + nt * 8 + 2 * qc;
#pragma unroll
            for (int h2 = 0; h2 < 2; h2++) {
                int row = m0 + wr * 32 + mt * 16 + qr + 8 * h2;
                float2 o = make_float2(acc[mt][nt][2 * h2],
                                       acc[mt][nt][2 * h2 + 1]);
                *(float2*)(C + (size_t)row * MDIM + col) = o;
            }
        }
    }
}

// =======================================================================
// One-shot tf32 GEMM for K=128 (steps 2 & 5)  (unchanged from R10)
// =======================================================================
#define EPI_SILU 1
#define EPI_RES  2
#define GT_SMEM  (2 * 128 * 132 * 4)    // 135168 B

template <int EPI, bool CVTA>
__global__ __launch_bounds__(256, 1)
void gemm_tf32_k128(const float* __restrict__ A, const float* __restrict__ B,
                    const float* __restrict__ bias, const float* __restrict__ X,
                    float* __restrict__ C, int N)
{
    extern __shared__ float sm[];
    float* sA = sm;
    float* sB = sm + 128 * 132;
    const uint32_t sA_u = smem_u32(sA);
    const uint32_t sB_u = smem_u32(sB);

    const int tid  = threadIdx.x;
    const int wid  = tid >> 5;
    const int lane = tid & 31;
    const int wr   = wid >> 2;
    const int wc   = wid & 3;
    const int qr   = lane >> 2;
    const int qc   = lane & 3;
    const int m0   = blockIdx.x * 128;
    const int n0   = blockIdx.y * 128;

    const int lt = lane >> 3;
    const int lr = lane & 7;
    const int a_off = (wr * 64 + (lt & 1) * 8 + lr) * 132 + (lt >> 1) * 4;
    const int b_off = (wc * 32 + (lt >> 1) * 8 + lr) * 132 + (lt & 1) * 4;

#pragma unroll
    for (int o = 0; o < 16; o++) {
        int li = o * 256 + tid;
        int row = li >> 5, g = li & 31;
        cp_async16(sA_u + (row * 132 + g * 4) * 4,
                   A + (size_t)(m0 + row) * MDIM + g * 4);
    }
#pragma unroll
    for (int o = 0; o < 16; o++) {
        int li = o * 256 + tid;
        int row = li >> 5, g = li & 31;
        cp_async16(sB_u + (row * 132 + g * 4) * 4,
                   B + (size_t)(n0 + row) * MDIM + g * 4);
    }
    cp_commit();

    float acc[4][4][4];
#pragma unroll
    for (int mt = 0; mt < 4; mt++)
#pragma unroll
        for (int nt = 0; nt < 4; nt++)
#pragma unroll
            for (int v = 0; v < 4; v++) acc[mt][nt][v] = 0.f;

    cp_wait<0>();
    __syncthreads();

#pragma unroll
    for (int k8 = 0; k8 < 16; k8++) {
        const int k0 = k8 * 8;
        uint32_t af[4][4], bf[4][2];
        if (CVTA) {
#pragma unroll
            for (int mt = 0; mt < 4; mt++) {
                const float* ar = sA + (wr * 64 + mt * 16 + qr) * 132 + k0 + qc;
                af[mt][0] = f2tf32(ar[0]);
                af[mt][1] = f2tf32(ar[8 * 132]);
                af[mt][2] = f2tf32(ar[4]);
                af[mt][3] = f2tf32(ar[8 * 132 + 4]);
            }
        } else {
#pragma unroll
            for (int mt = 0; mt < 4; mt++)
                ldsm_x4(af[mt][0], af[mt][1], af[mt][2], af[mt][3],
                        sA_u + (uint32_t)(a_off + mt * 16 * 132 + k0) * 4);
        }
#pragma unroll
        for (int p = 0; p < 2; p++) {
            uint32_t r0, r1, r2, r3;
            ldsm_x4(r0, r1, r2, r3,
                    sB_u + (uint32_t)(b_off + p * 16 * 132 + k0) * 4);
            bf[2 * p][0] = r0;  bf[2 * p][1] = r1;
            bf[2 * p + 1][0] = r2;  bf[2 * p + 1][1] = r3;
        }
#pragma unroll
        for (int mt = 0; mt < 4; mt++)
#pragma unroll
            for (int nt = 0; nt < 4; nt++)
                mma_tf32(acc[mt][nt], af[mt], bf[nt]);
    }

#pragma unroll
    for (int mt = 0; mt < 4; mt++) {
#pragma unroll
        for (int nt = 0; nt < 4; nt++) {
            int col = n0 + wc * 32 + nt * 8 + 2 * qc;
#pragma unroll
            for (int h2 = 0; h2 < 2; h2++) {
                int row = m0 + wr * 64 + mt * 16 + qr + 8 * h2;
                float v0 = acc[mt][nt][2 * h2];
                float v1 = acc[mt][nt][2 * h2 + 1];
                size_t base = (size_t)row * N + col;
                float2 o;
                if (EPI == EPI_SILU) {
                    float z0 = v0 + bias[col];
                    float z1 = v1 + bias[col + 1];
                    o.x = __uint_as_float(f2tf32(z0 / (1.f + expf(-z0))));
                    o.y = __uint_as_float(f2tf32(z1 / (1.f + expf(-z1))));
                } else {
                    float2 xv = *(const float2*)(X + base);
                    o.x = v0 + xv.x;
                    o.y = v1 + xv.y;
                }
                *(float2*)(C + base) = o;
            }
        }
    }
}

// =======================================================================
// K3, 2 CTAs/SM variant:
//   CTA tile 128(M) x 128(N) — N-tile == ALL 128 j's of ONE output column i.
//   C1[n, i*128+j] = sum_k h[n,k] * W2r[(i*128+j), k]    (NT GEMM, K=512)
//   feats2[n,i]    = round_tf32( sum_j (C1 + b2-term) * feats[n,j] )
// KC=32, 2-stage ring, stride-36 smem (4r+c covers 32 banks — conflict-free).
// smem 73728 B, launch_bounds(256,2) -> 2 CTAs/SM, 16 warps/SM.
// =======================================================================
#define K3_BM   128
#define K3_BN   128
#define K3_KC   32
#define K3_NCH  16                         // 512 / 32
#define K3_STR  36
#define K3_ASTG (K3_BM * K3_STR)           // 4608 floats
#define K3_BSTG (K3_BN * K3_STR)           // 4608 floats
#define K3_SMEM_BYTES (2 * (K3_ASTG + K3_BSTG) * 4)   // 73728 B

__global__ __launch_bounds__(256, 2)
void k3_mma(const float* __restrict__ W2r,
            const float* __restrict__ feats,
            const float* __restrict__ h,
            const float* __restrict__ b2,
            float* __restrict__ feats2)
{
    extern __shared__ float smf[];
    float* sAf = smf;                      // [2][4608]
    float* sBf = smf + 2 * K3_ASTG;        // [2][4608]
    const uint32_t sA_u = smem_u32(sAf);
    const uint32_t sB_u = smem_u32(sBf);

    const int tid  = threadIdx.x;
    const int wid  = tid >> 5;
    const int lane = tid & 31;
    const int wr   = wid >> 2;             // 0..1 -> rows 64*wr
    const int wc   = wid & 3;              // 0..3 -> j cols 32*wc
    const int qr   = lane >> 2;
    const int qc   = lane & 3;
    const int m0   = blockIdx.x * K3_BM;
    const int nb   = blockIdx.y;           // output column i

    const int lt = lane >> 3;
    const int lr = lane & 7;
    const int a_off = (wr * 64 + (lt & 1) * 8 + lr) * K3_STR + (lt >> 1) * 4;
    const int b_off = (wc * 32 + (lt >> 1) * 8 + lr) * K3_STR + (lt & 1) * 4;

    float acc[4][4][4];                    // 64 regs
#pragma unroll
    for (int mt = 0; mt < 4; mt++)
#pragma unroll
        for (int nt = 0; nt < 4; nt++)
#pragma unroll
            for (int v = 0; v < 4; v++) acc[mt][nt][v] = 0.f;

    // chunk = KC=32 cols: A 128 rows x 8 granules, B 128 rows x 8 granules
    auto load_chunk = [&](int c) {
        const int s = c & 1;
        const int kc = c * K3_KC;
        const uint32_t ab = sA_u + s * K3_ASTG * 4;
        const uint32_t bb = sB_u + s * K3_BSTG * 4;
#pragma unroll
        for (int o = 0; o < 4; o++) {
            int li = o * 256 + tid;
            int row = li >> 3, g = li & 7;
            cp_async16(ab + (row * K3_STR + g * 4) * 4,
                       h + (size_t)(m0 + row) * HDIM + kc + g * 4);
        }
#pragma unroll
        for (int o = 0; o < 4; o++) {
            int li = o * 256 + tid;
            int row = li >> 3, g = li & 7;
            cp_async16(bb + (row * K3_STR + g * 4) * 4,
                       W2r + (size_t)(nb * K3_BN + row) * HDIM + kc + g * 4);
        }
        cp_commit();
    };

    load_chunk(0);

    for (int c = 0; c < K3_NCH; c++) {
        cp_wait<0>();
        __syncthreads();
        if (c + 1 < K3_NCH) load_chunk(c + 1);

        const uint32_t ab = sA_u + (c & 1) * K3_ASTG * 4;
        const uint32_t bb = sB_u + (c & 1) * K3_BSTG * 4;

#pragma unroll
        for (int k8 = 0; k8 < 4; k8++) {
            const int k0 = k8 * 8;
            uint32_t af[4][4], bf[4][2];
#pragma unroll
            for (int mt = 0; mt < 4; mt++)
                ldsm_x4(af[mt][0], af[mt][1], af[mt][2], af[mt][3],
                        ab + (uint32_t)(a_off + mt * 16 * K3_STR + k0) * 4);
#pragma unroll
            for (int p = 0; p < 2; p++) {
                uint32_t r0, r1, r2, r3;
                ldsm_x4(r0, r1, r2, r3,
                        bb + (uint32_t)(b_off + p * 16 * K3_STR + k0) * 4);
                bf[2 * p][0] = r0;  bf[2 * p][1] = r1;
                bf[2 * p + 1][0] = r2;  bf[2 * p + 1][1] = r3;
            }
#pragma unroll
            for (int mt = 0; mt < 4; mt++)
#pragma unroll
                for (int nt = 0; nt < 4; nt++)
                    mma_tf32(acc[mt][nt], af[mt], bf[nt]);
        }
    }
    __syncthreads();   // all MMAs done before smem reuse below

    // ---- epilogue: stage feats [128][132] in smem, reduce over j ----
    float* fs   = smf;                          // 128*132 = 16896 floats (67.6KB)
    float* sRed = smf + 128 * 132;              // [128][4]
#pragma unroll
    for (int o = 0; o < 16; o++) {
        int li = o * 256 + tid;
        int row = li >> 5, g = li & 31;
        float4 v = *(const float4*)(feats + (size_t)(m0 + row) * MDIM + g * 4);
        float* d = fs + row * 132 + g * 4;
        d[0] = v.x; d[1] = v.y; d[2] = v.z; d[3] = v.w;
    }
    __syncthreads();

#pragma unroll
    for (int mt = 0; mt < 4; mt++) {
#pragma unroll
        for (int h2 = 0; h2 < 2; h2++) {
            int rl = wr * 64 + mt * 16 + qr + 8 * h2;
            float p = 0.f;
#pragma unroll
            for (int nt = 0; nt < 4; nt++) {
                int j0 = wc * 32 + nt * 8 + 2 * qc;
                p = fmaf(acc[mt][nt][2 * h2],     fs[rl * 132 + j0],     p);
                p = fmaf(acc[mt][nt][2 * h2 + 1], fs[rl * 132 + j0 + 1], p);
            }
            p += __shfl_xor_sync(0xffffffffu, p, 1);
            p += __shfl_xor_sync(0xffffffffu, p, 2);
            if (qc == 0) sRed[rl * 4 + wc] = p;
        }
    }
    __syncthreads();

    if (tid < 128) {
        int row = tid;
        float s = sRed[row * 4 + 0] + sRed[row * 4 + 1]
                + sRed[row * 4 + 2] + sRed[row * 4 + 3];
        // fold b2 bias term: + sum_j b2[nb*128 + j] * feats[row][j]
        const float4* bb2 = (const float4*)(b2 + (size_t)nb * MDIM);
        const float* fr = fs + row * 132;
        float bacc = 0.f;
#pragma unroll
        for (int j = 0; j < 32; j++) {
            float4 v = bb2[j];
            bacc = fmaf(v.x, fr[4 * j + 0],
                   fmaf(v.y, fr[4 * j + 1],
                   fmaf(v.z, fr[4 * j + 2],
                   fmaf(v.w, fr[4 * j + 3], bacc))));
        }
        feats2[(size_t)(m0 + row) * MDIM + nb] =
            __uint_as_float(f2tf32(s + bacc));
    }
}

// =======================================================================
// Host launcher
// =======================================================================
extern "C" void kernel_launch(void* const* d_in, const int* in_sizes, int n_in,
                              void* d_out, int out_size)
{
    const float* x    = (const float*)d_in[0];
    const float* Wmap = (const float*)d_in[1];
    const float* W1   = (const float*)d_in[2];
    const float* b1   = (const float*)d_in[3];
    const float* W2   = (const float*)d_in[4];
    const float* b2   = (const float*)d_in[5];
    float* out = (float*)d_out;

    void *pf, *ph, *pf2, *pwt, *pw2, *pw1, *pxh, *pxl, *pwh, *pwl;
    cudaGetSymbolAddress(&pf,  g_feats);
    cudaGetSymbolAddress(&ph,  g_h);
    cudaGetSymbolAddress(&pf2, g_feats2);
    cudaGetSymbolAddress(&pwt, g_wmapT);
    cudaGetSymbolAddress(&pw2, g_w2r);
    cudaGetSymbolAddress(&pw1, g_w1r);
    cudaGetSymbolAddress(&pxh, g_xhi);
    cudaGetSymbolAddress(&pxl, g_xlo);
    cudaGetSymbolAddress(&pwh, g_wmh);
    cudaGetSymbolAddress(&pwl, g_wml);
    float* feats  = (float*)pf;
    float* hbuf   = (float*)ph;
    float* feats2 = (float*)pf2;
    float* wmapT  = (float*)pwt;
    float* w2r    = (float*)pw2;
    float* w1r    = (float*)pw1;
    float* xhi    = (float*)pxh;
    float* xlo    = (float*)pxl;
    float* wmh    = (float*)pwh;
    float* wml    = (float*)pwl;

    cudaFuncSetAttribute(k3_mma, cudaFuncAttributeMaxDynamicSharedMemorySize,
                         K3_SMEM_BYTES);
    cudaFuncSetAttribute(gemm_3xtf32,
                         cudaFuncAttributeMaxDynamicSharedMemorySize, G3_SMEM);
    cudaFuncSetAttribute(gemm_tf32_k128<EPI_SILU, true>,
                         cudaFuncAttributeMaxDynamicSharedMemorySize, GT_SMEM);
    cudaFuncSetAttribute(gemm_tf32_k128<EPI_RES, false>,
                         cudaFuncAttributeMaxDynamicSharedMemorySize, GT_SMEM);

    dim3 blk(256);

    // 0a) pre-round W2, W1; split x and Wmap into tf32 hi/lo
    round_tf32_kernel<<<2048, blk>>>((const float4*)W2, (float4*)w2r,
                                     MDIM * MDIM * HDIM / 4);
    round_tf32_kernel<<<64, blk>>>((const float4*)W1, (float4*)w1r,
                                   4 * MDIM * MDIM / 4);
    split_tf32_kernel<<<2048, blk>>>((const float4*)x, (float4*)xhi,
                                     (float4*)xlo, NROWS * VDIM / 4);
    split_tf32_kernel<<<64, blk>>>((const float4*)Wmap, (float4*)wmh,
                                   (float4*)wml, MDIM * VDIM / 4);
    // 0b) WmapT = round(W_map^T)
    transpose_wmap<<<dim3(VDIM / 32, MDIM / 32), blk>>>(Wmap, wmapT);

    // 1) feats = x @ W_map^T  via 3xTF32  (fp32-grade accuracy)
    gemm_3xtf32<<<NROWS / 64, blk, G3_SMEM>>>(xhi, xlo, wmh, wml, feats);

    // 2) h = round(silu(feats @ W1^T + b1))  (tf32)
    gemm_tf32_k128<EPI_SILU, true><<<dim3(NROWS / 128, HDIM / 128), blk, GT_SMEM>>>(
        feats, w1r, b1, nullptr, hbuf, HDIM);

    // 3+4) feats2 = round(((h @ W2r^T) + b2-term) . feats)  — 2 CTAs/SM
    k3_mma<<<dim3(NROWS / K3_BM, MDIM), blk, K3_SMEM_BYTES>>>(
        w2r, feats, hbuf, b2, feats2);

    // 5) out = x + feats2 @ wmapT^T   (tf32, ldmatrix both operands)
    gemm_tf32_k128<EPI_RES, false><<<dim3(NROWS / 128, VDIM / 128), blk, GT_SMEM>>>(
        feats2, wmapT, nullptr, x, out, VDIM);
}

// round 14
// speedup vs baseline: 4.9968x; 1.0058x over previous
#include <cuda_runtime.h>
#include <cstdint>
#include <cstdio>

// Problem dims (fixed)
#define NROWS 8192
#define VDIM  2048
#define MDIM  128
#define HDIM  512

// Scratch (allocation-free rule: __device__ globals)
__device__ __align__(256) float g_feats [NROWS * MDIM];     // 4 MB
__device__ __align__(256) float g_h     [NROWS * HDIM];     // 16 MB (tf32-rounded)
__device__ __align__(256) float g_feats2[NROWS * MDIM];     // 4 MB (tf32-rounded)
__device__ __align__(256) float g_wmapT [VDIM * MDIM];      // 1 MB (tf32-rounded)
__device__ __align__(256) float g_w2r   [MDIM * MDIM * HDIM]; // 64 MB (tf32 W2)
__device__ __align__(256) float g_w1r   [4 * MDIM * MDIM];  // 256 KB (tf32 W1)
__device__ __align__(256) float g_xhi   [NROWS * VDIM];     // 64 MB (x hi part)
__device__ __align__(256) float g_xlo   [NROWS * VDIM];     // 64 MB (x lo part)
__device__ __align__(256) float g_wmh   [MDIM * VDIM];      // 1 MB (Wmap hi)
__device__ __align__(256) float g_wml   [MDIM * VDIM];      // 1 MB (Wmap lo)

// ---------------- common PTX helpers ----------------
__device__ __forceinline__ uint32_t smem_u32(const void* p) {
    uint32_t a;
    asm("{ .reg .u64 t; cvta.to.shared.u64 t, %1; cvt.u32.u64 %0, t; }"
        : "=r"(a) : "l"(p));
    return a;
}
__device__ __forceinline__ void cp_async16(uint32_t dst, const void* src) {
    asm volatile("cp.async.cg.shared.global [%0], [%1], 16;"
                 :: "r"(dst), "l"(src));
}
__device__ __forceinline__ void cp_commit() {
    asm volatile("cp.async.commit_group;" ::: "memory");
}
template <int N>
__device__ __forceinline__ void cp_wait() {
    asm volatile("cp.async.wait_group %0;" :: "n"(N) : "memory");
}
__device__ __forceinline__ uint32_t f2tf32(float f) {
    uint32_t r;
    asm("cvt.rna.tf32.f32 %0, %1;" : "=r"(r) : "f"(f));
    return r;
}
__device__ __forceinline__ void mma_tf32(float* d, const uint32_t* a,
                                         const uint32_t* b) {
    asm volatile(
        "mma.sync.aligned.m16n8k8.row.col.f32.tf32.tf32.f32 "
        "{%0,%1,%2,%3}, {%4,%5,%6,%7}, {%8,%9}, {%0,%1,%2,%3};"
        : "+f"(d[0]), "+f"(d[1]), "+f"(d[2]), "+f"(d[3])
        : "r"(a[0]), "r"(a[1]), "r"(a[2]), "r"(a[3]), "r"(b[0]), "r"(b[1]));
}
__device__ __forceinline__ void ldsm_x4(uint32_t& r0, uint32_t& r1,
                                        uint32_t& r2, uint32_t& r3,
                                        uint32_t addr) {
    asm volatile("ldmatrix.sync.aligned.m8n8.x4.shared.b16 {%0,%1,%2,%3}, [%4];"
                 : "=r"(r0), "=r"(r1), "=r"(r2), "=r"(r3) : "r"(addr));
}

// =======================================================================
// Pre-round a buffer to tf32 format
// =======================================================================
__global__ __launch_bounds__(256)
void round_tf32_kernel(const float4* __restrict__ in, float4* __restrict__ out,
                       int n4)
{
    int i = blockIdx.x * blockDim.x + threadIdx.x;
    int stride = gridDim.x * blockDim.x;
    for (; i < n4; i += stride) {
        float4 v = in[i];
        float4 o;
        o.x = __uint_as_float(f2tf32(v.x));
        o.y = __uint_as_float(f2tf32(v.y));
        o.z = __uint_as_float(f2tf32(v.z));
        o.w = __uint_as_float(f2tf32(v.w));
        out[i] = o;
    }
}

// =======================================================================
// 3xTF32 split: hi = rnd(v), lo = rnd(v - hi)
// =======================================================================
__global__ __launch_bounds__(256)
void split_tf32_kernel(const float4* __restrict__ in,
                       float4* __restrict__ hi, float4* __restrict__ lo,
                       int n4)
{
    int i = blockIdx.x * blockDim.x + threadIdx.x;
    int stride = gridDim.x * blockDim.x;
    for (; i < n4; i += stride) {
        float4 v = in[i];
        float4 h4, l4;
        h4.x = __uint_as_float(f2tf32(v.x)); l4.x = __uint_as_float(f2tf32(v.x - h4.x));
        h4.y = __uint_as_float(f2tf32(v.y)); l4.y = __uint_as_float(f2tf32(v.y - h4.y));
        h4.z = __uint_as_float(f2tf32(v.z)); l4.z = __uint_as_float(f2tf32(v.z - h4.z));
        h4.w = __uint_as_float(f2tf32(v.w)); l4.w = __uint_as_float(f2tf32(v.w - h4.w));
        hi[i] = h4;
        lo[i] = l4;
    }
}

// =======================================================================
// W_map transpose (+ tf32 round): WT[v][i] = round(W[i][v])
// =======================================================================
__global__ __launch_bounds__(256)
void transpose_wmap(const float* __restrict__ W, float* __restrict__ WT)
{
    __shared__ float t[32][33];
    const int bx = blockIdx.x * 32;   // v
    const int by = blockIdx.y * 32;   // i
    const int tx = threadIdx.x & 31;
    const int ty = threadIdx.x >> 5;  // 0..7
#pragma unroll
    for (int r = 0; r < 32; r += 8)
        t[ty + r][tx] = W[(size_t)(by + ty + r) * VDIM + bx + tx];
    __syncthreads();
#pragma unroll
    for (int r = 0; r < 32; r += 8)
        WT[(size_t)(bx + ty + r) * MDIM + by + tx] =
            __uint_as_float(f2tf32(t[tx][ty + r]));
}

// =======================================================================
// Step 1 via 3xTF32: feats = x @ Wmap^T with fp32-grade accuracy.
// (unchanged from R10)
// =======================================================================
#define G3_KC    64
#define G3_NCH   (VDIM / G3_KC)            // 32
#define G3_STR   68
#define G3_STAGE (384 * G3_STR)            // 26112 floats
#define G3_SMEM  (2 * G3_STAGE * 4)        // 208896 B

__global__ __launch_bounds__(256, 1)
void gemm_3xtf32(const float* __restrict__ xhi, const float* __restrict__ xlo,
                 const float* __restrict__ wmh, const float* __restrict__ wml,
                 float* __restrict__ C)
{
    extern __shared__ float smf[];
    const uint32_t s_u = smem_u32(smf);

    const int tid  = threadIdx.x;
    const int wid  = tid >> 5;
    const int lane = tid & 31;
    const int wr   = wid >> 2;
    const int wc   = wid & 3;
    const int qr   = lane >> 2;
    const int qc   = lane & 3;
    const int m0   = blockIdx.x * 64;

    const int lt = lane >> 3;
    const int lr = lane & 7;
    const int a_off = (wr * 32 + (lt & 1) * 8 + lr) * G3_STR + (lt >> 1) * 4;
    const int b_off = (wc * 32 + (lt >> 1) * 8 + lr) * G3_STR + (lt & 1) * 4;

    float acc[2][4][4];
#pragma unroll
    for (int mt = 0; mt < 2; mt++)
#pragma unroll
        for (int nt = 0; nt < 4; nt++)
#pragma unroll
            for (int v = 0; v < 4; v++) acc[mt][nt][v] = 0.f;

    auto load_chunk = [&](int c) {
        const int s = c & 1;
        const int kc = c * G3_KC;
        const uint32_t base = s_u + s * G3_STAGE * 4;
#pragma unroll
        for (int o = 0; o < 4; o++) {
            int li = o * 256 + tid;
            int row = li >> 4, g = li & 15;
            cp_async16(base + (row * G3_STR + g * 4) * 4,
                       xhi + (size_t)(m0 + row) * VDIM + kc + g * 4);
        }
#pragma unroll
        for (int o = 0; o < 4; o++) {
            int li = o * 256 + tid;
            int row = li >> 4, g = li & 15;
            cp_async16(base + ((64 + row) * G3_STR + g * 4) * 4,
                       xlo + (size_t)(m0 + row) * VDIM + kc + g * 4);
        }
#pragma unroll
        for (int o = 0; o < 8; o++) {
            int li = o * 256 + tid;
            int row = li >> 4, g = li & 15;
            cp_async16(base + ((128 + row) * G3_STR + g * 4) * 4,
                       wmh + (size_t)row * VDIM + kc + g * 4);
        }
#pragma unroll
        for (int o = 0; o < 8; o++) {
            int li = o * 256 + tid;
            int row = li >> 4, g = li & 15;
            cp_async16(base + ((256 + row) * G3_STR + g * 4) * 4,
                       wml + (size_t)row * VDIM + kc + g * 4);
        }
        cp_commit();
    };

    load_chunk(0);

    for (int c = 0; c < G3_NCH; c++) {
        cp_wait<0>();
        __syncthreads();
        if (c + 1 < G3_NCH) load_chunk(c + 1);

        const uint32_t base = s_u + (c & 1) * G3_STAGE * 4;
        const uint32_t aho = base + (uint32_t)a_off * 4;
        const uint32_t alo_ = aho + 64u * G3_STR * 4;
        const uint32_t bho = base + 128u * G3_STR * 4 + (uint32_t)b_off * 4;
        const uint32_t blo_ = bho + 128u * G3_STR * 4;

#pragma unroll
        for (int k8 = 0; k8 < 8; k8++) {
            const int k0 = k8 * 8;
            uint32_t ah[2][4], al[2][4], bh[4][2], bl[4][2];
#pragma unroll
            for (int mt = 0; mt < 2; mt++) {
                ldsm_x4(ah[mt][0], ah[mt][1], ah[mt][2], ah[mt][3],
                        aho + (uint32_t)(mt * 16 * G3_STR + k0) * 4);
                ldsm_x4(al[mt][0], al[mt][1], al[mt][2], al[mt][3],
                        alo_ + (uint32_t)(mt * 16 * G3_STR + k0) * 4);
            }
#pragma unroll
            for (int p = 0; p < 2; p++) {
                uint32_t r0, r1, r2, r3;
                ldsm_x4(r0, r1, r2, r3,
                        bho + (uint32_t)(p * 16 * G3_STR + k0) * 4);
                bh[2 * p][0] = r0;  bh[2 * p][1] = r1;
                bh[2 * p + 1][0] = r2;  bh[2 * p + 1][1] = r3;
                ldsm_x4(r0, r1, r2, r3,
                        blo_ + (uint32_t)(p * 16 * G3_STR + k0) * 4);
                bl[2 * p][0] = r0;  bl[2 * p][1] = r1;
                bl[2 * p + 1][0] = r2;  bl[2 * p + 1][1] = r3;
            }
#pragma unroll
            for (int mt = 0; mt < 2; mt++)
#pragma unroll
                for (int nt = 0; nt < 4; nt++) {
                    mma_tf32(acc[mt][nt], ah[mt], bh[nt]);
                    mma_tf32(acc[mt][nt], ah[mt], bl[nt]);
                    mma_tf32(acc[mt][nt], al[mt], bh[nt]);
                }
        }
    }

#pragma unroll
    for (int mt = 0; mt < 2; mt++) {
#pragma unroll
        for (int nt = 0; nt < 4; nt++) {
            int col = wc * 32 + nt * 8 + 2 * qc;
#pragma unroll
            for (int h2 = 0; h2 < 2; h2++) {
                int row = m0 + wr * 32 + mt * 16 + qr + 8 * h2;
                float2 o = make_float2(acc[mt][nt][2 * h2],
                                       acc[mt][nt][2 * h2 + 1]);
                *(float2*)(C + (size_t)row * MDIM + col) = o;
            }
        }
    }
}

// =======================================================================
// One-shot tf32 GEMM for K=128 (steps 2 & 5), v2: M-tile 64, 2 CTAs/SM.
//   C = epi(A[M,128] @ B[N,128]^T), tile 64(M) x 128(N).
// smem (64+128)*132*4 = 101376 B -> 2 CTAs/SM; acc 32 regs.
// Cross-CTA overlap hides the one-shot smem fill that bound the v1 shape.
// =======================================================================
#define EPI_SILU 1
#define EPI_RES  2
#define GT_SMEM  ((64 + 128) * 132 * 4)    // 101376 B

template <int EPI, bool CVTA>
__global__ __launch_bounds__(256, 2)
void gemm_tf32_k128(const float* __restrict__ A, const float* __restrict__ B,
                    const float* __restrict__ bias, const float* __restrict__ X,
                    float* __restrict__ C, int N)
{
    extern __shared__ float sm[];
    float* sA = sm;                  // [64][132]
    float* sB = sm + 64 * 132;       // [128][132]
    const uint32_t sA_u = smem_u32(sA);
    const uint32_t sB_u = smem_u32(sB);

    const int tid  = threadIdx.x;
    const int wid  = tid >> 5;
    const int lane = tid & 31;
    const int wr   = wid >> 2;       // 0..1 -> rows 32*wr
    const int wc   = wid & 3;        // 0..3 -> cols 32*wc
    const int qr   = lane >> 2;
    const int qc   = lane & 3;
    const int m0   = blockIdx.x * 64;
    const int n0   = blockIdx.y * 128;

    const int lt = lane >> 3;
    const int lr = lane & 7;
    const int a_off = (wr * 32 + (lt & 1) * 8 + lr) * 132 + (lt >> 1) * 4;
    const int b_off = (wc * 32 + (lt >> 1) * 8 + lr) * 132 + (lt & 1) * 4;

#pragma unroll
    for (int o = 0; o < 8; o++) {            // A: 64 rows x 32 granules
        int li = o * 256 + tid;
        int row = li >> 5, g = li & 31;
        cp_async16(sA_u + (row * 132 + g * 4) * 4,
                   A + (size_t)(m0 + row) * MDIM + g * 4);
    }
#pragma unroll
    for (int o = 0; o < 16; o++) {           // B: 128 rows x 32 granules
        int li = o * 256 + tid;
        int row = li >> 5, g = li & 31;
        cp_async16(sB_u + (row * 132 + g * 4) * 4,
                   B + (size_t)(n0 + row) * MDIM + g * 4);
    }
    cp_commit();

    float acc[2][4][4];
#pragma unroll
    for (int mt = 0; mt < 2; mt++)
#pragma unroll
        for (int nt = 0; nt < 4; nt++)
#pragma unroll
            for (int v = 0; v < 4; v++) acc[mt][nt][v] = 0.f;

    cp_wait<0>();
    __syncthreads();

#pragma unroll
    for (int k8 = 0; k8 < 16; k8++) {
        const int k0 = k8 * 8;
        uint32_t af[2][4], bf[4][2];
        if (CVTA) {
#pragma unroll
            for (int mt = 0; mt < 2; mt++) {
                const float* ar = sA + (wr * 32 + mt * 16 + qr) * 132 + k0 + qc;
                af[mt][0] = f2tf32(ar[0]);
                af[mt][1] = f2tf32(ar[8 * 132]);
                af[mt][2] = f2tf32(ar[4]);
                af[mt][3] = f2tf32(ar[8 * 132 + 4]);
            }
        } else {
#pragma unroll
            for (int mt = 0; mt < 2; mt++)
                ldsm_x4(af[mt][0], af[mt][1], af[mt][2], af[mt][3],
                        sA_u + (uint32_t)(a_off + mt * 16 * 132 + k0) * 4);
        }
#pragma unroll
        for (int p = 0; p < 2; p++) {
            uint32_t r0, r1, r2, r3;
            ldsm_x4(r0, r1, r2, r3,
                    sB_u + (uint32_t)(b_off + p * 16 * 132 + k0) * 4);
            bf[2 * p][0] = r0;  bf[2 * p][1] = r1;
            bf[2 * p + 1][0] = r2;  bf[2 * p + 1][1] = r3;
        }
#pragma unroll
        for (int mt = 0; mt < 2; mt++)
#pragma unroll
            for (int nt = 0; nt < 4; nt++)
                mma_tf32(acc[mt][nt], af[mt], bf[nt]);
    }

#pragma unroll
    for (int mt = 0; mt < 2; mt++) {
#pragma unroll
        for (int nt = 0; nt < 4; nt++) {
            int col = n0 + wc * 32 + nt * 8 + 2 * qc;
#pragma unroll
            for (int h2 = 0; h2 < 2; h2++) {
                int row = m0 + wr * 32 + mt * 16 + qr + 8 * h2;
                float v0 = acc[mt][nt][2 * h2];
                float v1 = acc[mt][nt][2 * h2 + 1];
                size_t base = (size_t)row * N + col;
                float2 o;
                if (EPI == EPI_SILU) {
                    float z0 = v0 + bias[col];
                    float z1 = v1 + bias[col + 1];
                    o.x = __uint_as_float(f2tf32(z0 / (1.f + expf(-z0))));
                    o.y = __uint_as_float(f2tf32(z1 / (1.f + expf(-z1))));
                } else {
                    float2 xv = *(const float2*)(X + base);
                    o.x = v0 + xv.x;
                    o.y = v1 + xv.y;
                }
                *(float2*)(C + base) = o;
            }
        }
    }
}

// =======================================================================
// K3, 2 CTAs/SM (unchanged from R13 — measured 713 us)
// =======================================================================
#define K3_BM   128
#define K3_BN   128
#define K3_KC   32
#define K3_NCH  16                         // 512 / 32
#define K3_STR  36
#define K3_ASTG (K3_BM * K3_STR)           // 4608 floats
#define K3_BSTG (K3_BN * K3_STR)           // 4608 floats
#define K3_SMEM_BYTES (2 * (K3_ASTG + K3_BSTG) * 4)   // 73728 B

__global__ __launch_bounds__(256, 2)
void k3_mma(const float* __restrict__ W2r,
            const float* __restrict__ feats,
            const float* __restrict__ h,
            const float* __restrict__ b2,
            float* __restrict__ feats2)
{
    extern __shared__ float smf[];
    float* sAf = smf;                      // [2][4608]
    float* sBf = smf + 2 * K3_ASTG;        // [2][4608]
    const uint32_t sA_u = smem_u32(sAf);
    const uint32_t sB_u = smem_u32(sBf);

    const int tid  = threadIdx.x;
    const int wid  = tid >> 5;
    const int lane = tid & 31;
    const int wr   = wid >> 2;             // 0..1 -> rows 64*wr
    const int wc   = wid & 3;              // 0..3 -> j cols 32*wc
    const int qr   = lane >> 2;
    const int qc   = lane & 3;
    const int m0   = blockIdx.x * K3_BM;
    const int nb   = blockIdx.y;           // output column i

    const int lt = lane >> 3;
    const int lr = lane & 7;
    const int a_off = (wr * 64 + (lt & 1) * 8 + lr) * K3_STR + (lt >> 1) * 4;
    const int b_off = (wc * 32 + (lt >> 1) * 8 + lr) * K3_STR + (lt & 1) * 4;

    float acc[4][4][4];                    // 64 regs
#pragma unroll
    for (int mt = 0; mt < 4; mt++)
#pragma unroll
        for (int nt = 0; nt < 4; nt++)
#pragma unroll
            for (int v = 0; v < 4; v++) acc[mt][nt][v] = 0.f;

    // chunk = KC=32 cols: A 128 rows x 8 granules, B 128 rows x 8 granules
    auto load_chunk = [&](int c) {
        const int s = c & 1;
        const int kc = c * K3_KC;
        const uint32_t ab = sA_u + s * K3_ASTG * 4;
        const uint32_t bb = sB_u + s * K3_BSTG * 4;
#pragma unroll
        for (int o = 0; o < 4; o++) {
            int li = o * 256 + tid;
            int row = li >> 3, g = li & 7;
            cp_async16(ab + (row * K3_STR + g * 4) * 4,
                       h + (size_t)(m0 + row) * HDIM + kc + g * 4);
        }
#pragma unroll
        for (int o = 0; o < 4; o++) {
            int li = o * 256 + tid;
            int row = li >> 3, g = li & 7;
            cp_async16(bb + (row * K3_STR + g * 4) * 4,
                       W2r + (size_t)(nb * K3_BN + row) * HDIM + kc + g * 4);
        }
        cp_commit();
    };

    load_chunk(0);

    for (int c = 0; c < K3_NCH; c++) {
        cp_wait<0>();
        __syncthreads();
        if (c + 1 < K3_NCH) load_chunk(c + 1);

        const uint32_t ab = sA_u + (c & 1) * K3_ASTG * 4;
        const uint32_t bb = sB_u + (c & 1) * K3_BSTG * 4;

#pragma unroll
        for (int k8 = 0; k8 < 4; k8++) {
            const int k0 = k8 * 8;
            uint32_t af[4][4], bf[4][2];
#pragma unroll
            for (int mt = 0; mt < 4; mt++)
                ldsm_x4(af[mt][0], af[mt][1], af[mt][2], af[mt][3],
                        ab + (uint32_t)(a_off + mt * 16 * K3_STR + k0) * 4);
#pragma unroll
            for (int p = 0; p < 2; p++) {
                uint32_t r0, r1, r2, r3;
                ldsm_x4(r0, r1, r2, r3,
                        bb + (uint32_t)(b_off + p * 16 * K3_STR + k0) * 4);
                bf[2 * p][0] = r0;  bf[2 * p][1] = r1;
                bf[2 * p + 1][0] = r2;  bf[2 * p + 1][1] = r3;
            }
#pragma unroll
            for (int mt = 0; mt < 4; mt++)
#pragma unroll
                for (int nt = 0; nt < 4; nt++)
                    mma_tf32(acc[mt][nt], af[mt], bf[nt]);
        }
    }
    __syncthreads();   // all MMAs done before smem reuse below

    // ---- epilogue: stage feats [128][132] in smem, reduce over j ----
    float* fs   = smf;                          // 128*132 = 16896 floats (67.6KB)
    float* sRed = smf + 128 * 132;              // [128][4]
#pragma unroll
    for (int o = 0; o < 16; o++) {
        int li = o * 256 + tid;
        int row = li >> 5, g = li & 31;
        float4 v = *(const float4*)(feats + (size_t)(m0 + row) * MDIM + g * 4);
        float* d = fs + row * 132 + g * 4;
        d[0] = v.x; d[1] = v.y; d[2] = v.z; d[3] = v.w;
    }
    __syncthreads();

#pragma unroll
    for (int mt = 0; mt < 4; mt++) {
#pragma unroll
        for (int h2 = 0; h2 < 2; h2++) {
            int rl = wr * 64 + mt * 16 + qr + 8 * h2;
            float p = 0.f;
#pragma unroll
            for (int nt = 0; nt < 4; nt++) {
                int j0 = wc * 32 + nt * 8 + 2 * qc;
                p = fmaf(acc[mt][nt][2 * h2],     fs[rl * 132 + j0],     p);
                p = fmaf(acc[mt][nt][2 * h2 + 1], fs[rl * 132 + j0 + 1], p);
            }
            p += __shfl_xor_sync(0xffffffffu, p, 1);
            p += __shfl_xor_sync(0xffffffffu, p, 2);
            if (qc == 0) sRed[rl * 4 + wc] = p;
        }
    }
    __syncthreads();

    if (tid < 128) {
        int row = tid;
        float s = sRed[row * 4 + 0] + sRed[row * 4 + 1]
                + sRed[row * 4 + 2] + sRed[row * 4 + 3];
        // fold b2 bias term: + sum_j b2[nb*128 + j] * feats[row][j]
        const float4* bb2 = (const float4*)(b2 + (size_t)nb * MDIM);
        const float* fr = fs + row * 132;
        float bacc = 0.f;
#pragma unroll
        for (int j = 0; j < 32; j++) {
            float4 v = bb2[j];
            bacc = fmaf(v.x, fr[4 * j + 0],
                   fmaf(v.y, fr[4 * j + 1],
                   fmaf(v.z, fr[4 * j + 2],
                   fmaf(v.w, fr[4 * j + 3], bacc))));
        }
        feats2[(size_t)(m0 + row) * MDIM + nb] =
            __uint_as_float(f2tf32(s + bacc));
    }
}

// =======================================================================
// Host launcher
// =======================================================================
extern "C" void kernel_launch(void* const* d_in, const int* in_sizes, int n_in,
                              void* d_out, int out_size)
{
    const float* x    = (const float*)d_in[0];
    const float* Wmap = (const float*)d_in[1];
    const float* W1   = (const float*)d_in[2];
    const float* b1   = (const float*)d_in[3];
    const float* W2   = (const float*)d_in[4];
    const float* b2   = (const float*)d_in[5];
    float* out = (float*)d_out;

    void *pf, *ph, *pf2, *pwt, *pw2, *pw1, *pxh, *pxl, *pwh, *pwl;
    cudaGetSymbolAddress(&pf,  g_feats);
    cudaGetSymbolAddress(&ph,  g_h);
    cudaGetSymbolAddress(&pf2, g_feats2);
    cudaGetSymbolAddress(&pwt, g_wmapT);
    cudaGetSymbolAddress(&pw2, g_w2r);
    cudaGetSymbolAddress(&pw1, g_w1r);
    cudaGetSymbolAddress(&pxh, g_xhi);
    cudaGetSymbolAddress(&pxl, g_xlo);
    cudaGetSymbolAddress(&pwh, g_wmh);
    cudaGetSymbolAddress(&pwl, g_wml);
    float* feats  = (float*)pf;
    float* hbuf   = (float*)ph;
    float* feats2 = (float*)pf2;
    float* wmapT  = (float*)pwt;
    float* w2r    = (float*)pw2;
    float* w1r    = (float*)pw1;
    float* xhi    = (float*)pxh;
    float* xlo    = (float*)pxl;
    float* wmh    = (float*)pwh;
    float* wml    = (float*)pwl;

    cudaFuncSetAttribute(k3_mma, cudaFuncAttributeMaxDynamicSharedMemorySize,
                         K3_SMEM_BYTES);
    cudaFuncSetAttribute(gemm_3xtf32,
                         cudaFuncAttributeMaxDynamicSharedMemorySize, G3_SMEM);
    cudaFuncSetAttribute(gemm_tf32_k128<EPI_SILU, true>,
                         cudaFuncAttributeMaxDynamicSharedMemorySize, GT_SMEM);
    cudaFuncSetAttribute(gemm_tf32_k128<EPI_RES, false>,
                         cudaFuncAttributeMaxDynamicSharedMemorySize, GT_SMEM);

    dim3 blk(256);

    // 0a) pre-round W2, W1; split x and Wmap into tf32 hi/lo
    round_tf32_kernel<<<2048, blk>>>((const float4*)W2, (float4*)w2r,
                                     MDIM * MDIM * HDIM / 4);
    round_tf32_kernel<<<64, blk>>>((const float4*)W1, (float4*)w1r,
                                   4 * MDIM * MDIM / 4);
    split_tf32_kernel<<<2048, blk>>>((const float4*)x, (float4*)xhi,
                                     (float4*)xlo, NROWS * VDIM / 4);
    split_tf32_kernel<<<64, blk>>>((const float4*)Wmap, (float4*)wmh,
                                   (float4*)wml, MDIM * VDIM / 4);
    // 0b) WmapT = round(W_map^T)
    transpose_wmap<<<dim3(VDIM / 32, MDIM / 32), blk>>>(Wmap, wmapT);

    // 1) feats = x @ W_map^T  via 3xTF32  (fp32-grade accuracy)
    gemm_3xtf32<<<NROWS / 64, blk, G3_SMEM>>>(xhi, xlo, wmh, wml, feats);

    // 2) h = round(silu(feats @ W1^T + b1))  (tf32, M64 tiles, 2 CTAs/SM)
    gemm_tf32_k128<EPI_SILU, true><<<dim3(NROWS / 64, HDIM / 128), blk, GT_SMEM>>>(
        feats, w1r, b1, nullptr, hbuf, HDIM);

    // 3+4) feats2 = round(((h @ W2r^T) + b2-term) . feats)  — 2 CTAs/SM
    k3_mma<<<dim3(NROWS / K3_BM, MDIM), blk, K3_SMEM_BYTES>>>(
        w2r, feats, hbuf, b2, feats2);

    // 5) out = x + feats2 @ wmapT^T   (tf32, M64 tiles, 2 CTAs/SM)
    gemm_tf32_k128<EPI_RES, false><<<dim3(NROWS / 64, VDIM / 128), blk, GT_SMEM>>>(
        feats2, wmapT, nullptr, x, out, VDIM);
}

// round 15
// speedup vs baseline: 5.1345x; 1.0276x over previous
#include <cuda_runtime.h>
#include <cstdint>
#include <cstdio>

// Problem dims (fixed)
#define NROWS 8192
#define VDIM  2048
#define MDIM  128
#define HDIM  512

// Scratch (allocation-free rule: __device__ globals)
__device__ __align__(256) float g_feats [NROWS * MDIM];     // 4 MB
__device__ __align__(256) float g_h     [NROWS * HDIM];     // 16 MB (tf32-rounded)
__device__ __align__(256) float g_feats2[NROWS * MDIM];     // 4 MB (tf32-rounded)
__device__ __align__(256) float g_wmapT [VDIM * MDIM];      // 1 MB (tf32-rounded)
__device__ __align__(256) float g_w2r   [MDIM * MDIM * HDIM]; // 64 MB (tf32 W2)
__device__ __align__(256) float g_w1r   [4 * MDIM * MDIM];  // 256 KB (tf32 W1)
__device__ __align__(256) float g_wmh   [MDIM * VDIM];      // 1 MB (Wmap hi)
__device__ __align__(256) float g_wml   [MDIM * VDIM];      // 1 MB (Wmap lo)

// ---------------- common PTX helpers ----------------
__device__ __forceinline__ uint32_t smem_u32(const void* p) {
    uint32_t a;
    asm("{ .reg .u64 t; cvta.to.shared.u64 t, %1; cvt.u32.u64 %0, t; }"
        : "=r"(a) : "l"(p));
    return a;
}
__device__ __forceinline__ void cp_async16(uint32_t dst, const void* src) {
    asm volatile("cp.async.cg.shared.global [%0], [%1], 16;"
                 :: "r"(dst), "l"(src));
}
__device__ __forceinline__ void cp_commit() {
    asm volatile("cp.async.commit_group;" ::: "memory");
}
template <int N>
__device__ __forceinline__ void cp_wait() {
    asm volatile("cp.async.wait_group %0;" :: "n"(N) : "memory");
}
__device__ __forceinline__ uint32_t f2tf32(float f) {
    uint32_t r;
    asm("cvt.rna.tf32.f32 %0, %1;" : "=r"(r) : "f"(f));
    return r;
}
__device__ __forceinline__ void mma_tf32(float* d, const uint32_t* a,
                                         const uint32_t* b) {
    asm volatile(
        "mma.sync.aligned.m16n8k8.row.col.f32.tf32.tf32.f32 "
        "{%0,%1,%2,%3}, {%4,%5,%6,%7}, {%8,%9}, {%0,%1,%2,%3};"
        : "+f"(d[0]), "+f"(d[1]), "+f"(d[2]), "+f"(d[3])
        : "r"(a[0]), "r"(a[1]), "r"(a[2]), "r"(a[3]), "r"(b[0]), "r"(b[1]));
}
__device__ __forceinline__ void ldsm_x4(uint32_t& r0, uint32_t& r1,
                                        uint32_t& r2, uint32_t& r3,
                                        uint32_t addr) {
    asm volatile("ldmatrix.sync.aligned.m8n8.x4.shared.b16 {%0,%1,%2,%3}, [%4];"
                 : "=r"(r0), "=r"(r1), "=r"(r2), "=r"(r3) : "r"(addr));
}

// =======================================================================
// Pre-round a buffer to tf32 format
// =======================================================================
__global__ __launch_bounds__(256)
void round_tf32_kernel(const float4* __restrict__ in, float4* __restrict__ out,
                       int n4)
{
    int i = blockIdx.x * blockDim.x + threadIdx.x;
    int stride = gridDim.x * blockDim.x;
    for (; i < n4; i += stride) {
        float4 v = in[i];
        float4 o;
        o.x = __uint_as_float(f2tf32(v.x));
        o.y = __uint_as_float(f2tf32(v.y));
        o.z = __uint_as_float(f2tf32(v.z));
        o.w = __uint_as_float(f2tf32(v.w));
        out[i] = o;
    }
}

// =======================================================================
// 3xTF32 split (W_map only now): hi = rnd(v), lo = rnd(v - hi)
// =======================================================================
__global__ __launch_bounds__(256)
void split_tf32_kernel(const float4* __restrict__ in,
                       float4* __restrict__ hi, float4* __restrict__ lo,
                       int n4)
{
    int i = blockIdx.x * blockDim.x + threadIdx.x;
    int stride = gridDim.x * blockDim.x;
    for (; i < n4; i += stride) {
        float4 v = in[i];
        float4 h4, l4;
        h4.x = __uint_as_float(f2tf32(v.x)); l4.x = __uint_as_float(f2tf32(v.x - h4.x));
        h4.y = __uint_as_float(f2tf32(v.y)); l4.y = __uint_as_float(f2tf32(v.y - h4.y));
        h4.z = __uint_as_float(f2tf32(v.z)); l4.z = __uint_as_float(f2tf32(v.z - h4.z));
        h4.w = __uint_as_float(f2tf32(v.w)); l4.w = __uint_as_float(f2tf32(v.w - h4.w));
        hi[i] = h4;
        lo[i] = l4;
    }
}

// =======================================================================
// W_map transpose (+ tf32 round): WT[v][i] = round(W[i][v])
// =======================================================================
__global__ __launch_bounds__(256)
void transpose_wmap(const float* __restrict__ W, float* __restrict__ WT)
{
    __shared__ float t[32][33];
    const int bx = blockIdx.x * 32;   // v
    const int by = blockIdx.y * 32;   // i
    const int tx = threadIdx.x & 31;
    const int ty = threadIdx.x >> 5;  // 0..7
#pragma unroll
    for (int r = 0; r < 32; r += 8)
        t[ty + r][tx] = W[(size_t)(by + ty + r) * VDIM + bx + tx];
    __syncthreads();
#pragma unroll
    for (int r = 0; r < 32; r += 8)
        WT[(size_t)(bx + ty + r) * MDIM + by + tx] =
            __uint_as_float(f2tf32(t[tx][ty + r]));
}

// =======================================================================
// Step 1 via 3xTF32 with FUSED x split:
//   feats = x @ Wmap^T;  xhi/xlo derived in registers from raw x fragments:
//   hi = rnd(x), lo = rnd(x - hi)  (bit-identical to the old pre-split).
// Stage: x raw [0,64) rows, Bhi [64,192), Blo [192,320), stride 68.
// M-tile 64, KC=64, 2-stage cp.async ring, ldmatrix.
// =======================================================================
#define G3_KC    64
#define G3_NCH   (VDIM / G3_KC)            // 32
#define G3_STR   68
#define G3_STAGE (320 * G3_STR)            // 21760 floats
#define G3_SMEM  (2 * G3_STAGE * 4)        // 174080 B

__global__ __launch_bounds__(256, 1)
void gemm_3xtf32(const float* __restrict__ x,
                 const float* __restrict__ wmh, const float* __restrict__ wml,
                 float* __restrict__ C)
{
    extern __shared__ float smf[];
    const uint32_t s_u = smem_u32(smf);

    const int tid  = threadIdx.x;
    const int wid  = tid >> 5;
    const int lane = tid & 31;
    const int wr   = wid >> 2;
    const int wc   = wid & 3;
    const int qr   = lane >> 2;
    const int qc   = lane & 3;
    const int m0   = blockIdx.x * 64;

    const int lt = lane >> 3;
    const int lr = lane & 7;
    const int a_off = (wr * 32 + (lt & 1) * 8 + lr) * G3_STR + (lt >> 1) * 4;
    const int b_off = (wc * 32 + (lt >> 1) * 8 + lr) * G3_STR + (lt & 1) * 4;

    float acc[2][4][4];
#pragma unroll
    for (int mt = 0; mt < 2; mt++)
#pragma unroll
        for (int nt = 0; nt < 4; nt++)
#pragma unroll
            for (int v = 0; v < 4; v++) acc[mt][nt][v] = 0.f;

    auto load_chunk = [&](int c) {
        const int s = c & 1;
        const int kc = c * G3_KC;
        const uint32_t base = s_u + s * G3_STAGE * 4;
#pragma unroll
        for (int o = 0; o < 4; o++) {       // x raw: 64 rows x 16 granules
            int li = o * 256 + tid;
            int row = li >> 4, g = li & 15;
            cp_async16(base + (row * G3_STR + g * 4) * 4,
                       x + (size_t)(m0 + row) * VDIM + kc + g * 4);
        }
#pragma unroll
        for (int o = 0; o < 8; o++) {       // B hi: 128 rows x 16 granules
            int li = o * 256 + tid;
            int row = li >> 4, g = li & 15;
            cp_async16(base + ((64 + row) * G3_STR + g * 4) * 4,
                       wmh + (size_t)row * VDIM + kc + g * 4);
        }
#pragma unroll
        for (int o = 0; o < 8; o++) {       // B lo
            int li = o * 256 + tid;
            int row = li >> 4, g = li & 15;
            cp_async16(base + ((192 + row) * G3_STR + g * 4) * 4,
                       wml + (size_t)row * VDIM + kc + g * 4);
        }
        cp_commit();
    };

    load_chunk(0);

    for (int c = 0; c < G3_NCH; c++) {
        cp_wait<0>();
        __syncthreads();
        if (c + 1 < G3_NCH) load_chunk(c + 1);

        const uint32_t base = s_u + (c & 1) * G3_STAGE * 4;
        const uint32_t axo = base + (uint32_t)a_off * 4;
        const uint32_t bho = base + 64u * G3_STR * 4 + (uint32_t)b_off * 4;
        const uint32_t blo_ = base + 192u * G3_STR * 4 + (uint32_t)b_off * 4;

#pragma unroll
        for (int k8 = 0; k8 < 8; k8++) {
            const int k0 = k8 * 8;
            uint32_t ah[2][4], al[2][4], bh[4][2], bl[4][2];
#pragma unroll
            for (int mt = 0; mt < 2; mt++) {
                uint32_t ar[4];
                ldsm_x4(ar[0], ar[1], ar[2], ar[3],
                        axo + (uint32_t)(mt * 16 * G3_STR + k0) * 4);
#pragma unroll
                for (int e = 0; e < 4; e++) {
                    float f  = __uint_as_float(ar[e]);
                    uint32_t hb = f2tf32(f);
                    ah[mt][e] = hb;
                    al[mt][e] = f2tf32(f - __uint_as_float(hb));
                }
            }
#pragma unroll
            for (int p = 0; p < 2; p++) {
                uint32_t r0, r1, r2, r3;
                ldsm_x4(r0, r1, r2, r3,
                        bho + (uint32_t)(p * 16 * G3_STR + k0) * 4);
                bh[2 * p][0] = r0;  bh[2 * p][1] = r1;
                bh[2 * p + 1][0] = r2;  bh[2 * p + 1][1] = r3;
                ldsm_x4(r0, r1, r2, r3,
                        blo_ + (uint32_t)(p * 16 * G3_STR + k0) * 4);
                bl[2 * p][0] = r0;  bl[2 * p][1] = r1;
                bl[2 * p + 1][0] = r2;  bl[2 * p + 1][1] = r3;
            }
#pragma unroll
            for (int mt = 0; mt < 2; mt++)
#pragma unroll
                for (int nt = 0; nt < 4; nt++) {
                    mma_tf32(acc[mt][nt], ah[mt], bh[nt]);
                    mma_tf32(acc[mt][nt], ah[mt], bl[nt]);
                    mma_tf32(acc[mt][nt], al[mt], bh[nt]);
                }
        }
    }

#pragma unroll
    for (int mt = 0; mt < 2; mt++) {
#pragma unroll
        for (int nt = 0; nt < 4; nt++) {
            int col = wc * 32 + nt * 8 + 2 * qc;
#pragma unroll
            for (int h2 = 0; h2 < 2; h2++) {
                int row = m0 + wr * 32 + mt * 16 + qr + 8 * h2;
                float2 o = make_float2(acc[mt][nt][2 * h2],
                                       acc[mt][nt][2 * h2 + 1]);
                *(float2*)(C + (size_t)row * MDIM + col) = o;
            }
        }
    }
}

// =======================================================================
// One-shot tf32 GEMM for K=128 (steps 2 & 5)  (unchanged from R14)
// =======================================================================
#define EPI_SILU 1
#define EPI_RES  2
#define GT_SMEM  ((64 + 128) * 132 * 4)    // 101376 B

template <int EPI, bool CVTA>
__global__ __launch_bounds__(256, 2)
void gemm_tf32_k128(const float* __restrict__ A, const float* __restrict__ B,
                    const float* __restrict__ bias, const float* __restrict__ X,
                    float* __restrict__ C, int N)
{
    extern __shared__ float sm[];
    float* sA = sm;                  // [64][132]
    float* sB = sm + 64 * 132;       // [128][132]
    const uint32_t sA_u = smem_u32(sA);
    const uint32_t sB_u = smem_u32(sB);

    const int tid  = threadIdx.x;
    const int wid  = tid >> 5;
    const int lane = tid & 31;
    const int wr   = wid >> 2;
    const int wc   = wid & 3;
    const int qr   = lane >> 2;
    const int qc   = lane & 3;
    const int m0   = blockIdx.x * 64;
    const int n0   = blockIdx.y * 128;

    const int lt = lane >> 3;
    const int lr = lane & 7;
    const int a_off = (wr * 32 + (lt & 1) * 8 + lr) * 132 + (lt >> 1) * 4;
    const int b_off = (wc * 32 + (lt >> 1) * 8 + lr) * 132 + (lt & 1) * 4;

#pragma unroll
    for (int o = 0; o < 8; o++) {
        int li = o * 256 + tid;
        int row = li >> 5, g = li & 31;
        cp_async16(sA_u + (row * 132 + g * 4) * 4,
                   A + (size_t)(m0 + row) * MDIM + g * 4);
    }
#pragma unroll
    for (int o = 0; o < 16; o++) {
        int li = o * 256 + tid;
        int row = li >> 5, g = li & 31;
        cp_async16(sB_u + (row * 132 + g * 4) * 4,
                   B + (size_t)(n0 + row) * MDIM + g * 4);
    }
    cp_commit();

    float acc[2][4][4];
#pragma unroll
    for (int mt = 0; mt < 2; mt++)
#pragma unroll
        for (int nt = 0; nt < 4; nt++)
#pragma unroll
            for (int v = 0; v < 4; v++) acc[mt][nt][v] = 0.f;

    cp_wait<0>();
    __syncthreads();

#pragma unroll
    for (int k8 = 0; k8 < 16; k8++) {
        const int k0 = k8 * 8;
        uint32_t af[2][4], bf[4][2];
        if (CVTA) {
#pragma unroll
            for (int mt = 0; mt < 2; mt++) {
                const float* ar = sA + (wr * 32 + mt * 16 + qr) * 132 + k0 + qc;
                af[mt][0] = f2tf32(ar[0]);
                af[mt][1] = f2tf32(ar[8 * 132]);
                af[mt][2] = f2tf32(ar[4]);
                af[mt][3] = f2tf32(ar[8 * 132 + 4]);
            }
        } else {
#pragma unroll
            for (int mt = 0; mt < 2; mt++)
                ldsm_x4(af[mt][0], af[mt][1], af[mt][2], af[mt][3],
                        sA_u + (uint32_t)(a_off + mt * 16 * 132 + k0) * 4);
        }
#pragma unroll
        for (int p = 0; p < 2; p++) {
            uint32_t r0, r1, r2, r3;
            ldsm_x4(r0, r1, r2, r3,
                    sB_u + (uint32_t)(b_off + p * 16 * 132 + k0) * 4);
            bf[2 * p][0] = r0;  bf[2 * p][1] = r1;
            bf[2 * p + 1][0] = r2;  bf[2 * p + 1][1] = r3;
        }
#pragma unroll
        for (int mt = 0; mt < 2; mt++)
#pragma unroll
            for (int nt = 0; nt < 4; nt++)
                mma_tf32(acc[mt][nt], af[mt], bf[nt]);
    }

#pragma unroll
    for (int mt = 0; mt < 2; mt++) {
#pragma unroll
        for (int nt = 0; nt < 4; nt++) {
            int col = n0 + wc * 32 + nt * 8 + 2 * qc;
#pragma unroll
            for (int h2 = 0; h2 < 2; h2++) {
                int row = m0 + wr * 32 + mt * 16 + qr + 8 * h2;
                float v0 = acc[mt][nt][2 * h2];
                float v1 = acc[mt][nt][2 * h2 + 1];
                size_t base = (size_t)row * N + col;
                float2 o;
                if (EPI == EPI_SILU) {
                    float z0 = v0 + bias[col];
                    float z1 = v1 + bias[col + 1];
                    o.x = __uint_as_float(f2tf32(z0 / (1.f + expf(-z0))));
                    o.y = __uint_as_float(f2tf32(z1 / (1.f + expf(-z1))));
                } else {
                    float2 xv = *(const float2*)(X + base);
                    o.x = v0 + xv.x;
                    o.y = v1 + xv.y;
                }
                *(float2*)(C + base) = o;
            }
        }
    }
}

// =======================================================================
// K3, 2 CTAs/SM (unchanged from R13 — measured ~713 us)
// =======================================================================
#define K3_BM   128
#define K3_BN   128
#define K3_KC   32
#define K3_NCH  16                         // 512 / 32
#define K3_STR  36
#define K3_ASTG (K3_BM * K3_STR)           // 4608 floats
#define K3_BSTG (K3_BN * K3_STR)           // 4608 floats
#define K3_SMEM_BYTES (2 * (K3_ASTG + K3_BSTG) * 4)   // 73728 B

__global__ __launch_bounds__(256, 2)
void k3_mma(const float* __restrict__ W2r,
            const float* __restrict__ feats,
            const float* __restrict__ h,
            const float* __restrict__ b2,
            float* __restrict__ feats2)
{
    extern __shared__ float smf[];
    float* sAf = smf;                      // [2][4608]
    float* sBf = smf + 2 * K3_ASTG;        // [2][4608]
    const uint32_t sA_u = smem_u32(sAf);
    const uint32_t sB_u = smem_u32(sBf);

    const int tid  = threadIdx.x;
    const int wid  = tid >> 5;
    const int lane = tid & 31;
    const int wr   = wid >> 2;             // 0..1 -> rows 64*wr
    const int wc   = wid & 3;              // 0..3 -> j cols 32*wc
    const int qr   = lane >> 2;
    const int qc   = lane & 3;
    const int m0   = blockIdx.x * K3_BM;
    const int nb   = blockIdx.y;           // output column i

    const int lt = lane >> 3;
    const int lr = lane & 7;
    const int a_off = (wr * 64 + (lt & 1) * 8 + lr) * K3_STR + (lt >> 1) * 4;
    const int b_off = (wc * 32 + (lt >> 1) * 8 + lr) * K3_STR + (lt & 1) * 4;

    float acc[4][4][4];                    // 64 regs
#pragma unroll
    for (int mt = 0; mt < 4; mt++)
#pragma unroll
        for (int nt = 0; nt < 4; nt++)
#pragma unroll
            for (int v = 0; v < 4; v++) acc[mt][nt][v] = 0.f;

    auto load_chunk = [&](int c) {
        const int s = c & 1;
        const int kc = c * K3_KC;
        const uint32_t ab = sA_u + s * K3_ASTG * 4;
        const uint32_t bb = sB_u + s * K3_BSTG * 4;
#pragma unroll
        for (int o = 0; o < 4; o++) {
            int li = o * 256 + tid;
            int row = li >> 3, g = li & 7;
            cp_async16(ab + (row * K3_STR + g * 4) * 4,
                       h + (size_t)(m0 + row) * HDIM + kc + g * 4);
        }
#pragma unroll
        for (int o = 0; o < 4; o++) {
            int li = o * 256 + tid;
            int row = li >> 3, g = li & 7;
            cp_async16(bb + (row * K3_STR + g * 4) * 4,
                       W2r + (size_t)(nb * K3_BN + row) * HDIM + kc + g * 4);
        }
        cp_commit();
    };

    load_chunk(0);

    for (int c = 0; c < K3_NCH; c++) {
        cp_wait<0>();
        __syncthreads();
        if (c + 1 < K3_NCH) load_chunk(c + 1);

        const uint32_t ab = sA_u + (c & 1) * K3_ASTG * 4;
        const uint32_t bb = sB_u + (c & 1) * K3_BSTG * 4;

#pragma unroll
        for (int k8 = 0; k8 < 4; k8++) {
            const int k0 = k8 * 8;
            uint32_t af[4][4], bf[4][2];
#pragma unroll
            for (int mt = 0; mt < 4; mt++)
                ldsm_x4(af[mt][0], af[mt][1], af[mt][2], af[mt][3],
                        ab + (uint32_t)(a_off + mt * 16 * K3_STR + k0) * 4);
#pragma unroll
            for (int p = 0; p < 2; p++) {
                uint32_t r0, r1, r2, r3;
                ldsm_x4(r0, r1, r2, r3,
                        bb + (uint32_t)(b_off + p * 16 * K3_STR + k0) * 4);
                bf[2 * p][0] = r0;  bf[2 * p][1] = r1;
                bf[2 * p + 1][0] = r2;  bf[2 * p + 1][1] = r3;
            }
#pragma unroll
            for (int mt = 0; mt < 4; mt++)
#pragma unroll
                for (int nt = 0; nt < 4; nt++)
                    mma_tf32(acc[mt][nt], af[mt], bf[nt]);
        }
    }
    __syncthreads();   // all MMAs done before smem reuse below

    // ---- epilogue: stage feats [128][132] in smem, reduce over j ----
    float* fs   = smf;                          // 128*132 floats
    float* sRed = smf + 128 * 132;              // [128][4]
#pragma unroll
    for (int o = 0; o < 16; o++) {
        int li = o * 256 + tid;
        int row = li >> 5, g = li & 31;
        float4 v = *(const float4*)(feats + (size_t)(m0 + row) * MDIM + g * 4);
        float* d = fs + row * 132 + g * 4;
        d[0] = v.x; d[1] = v.y; d[2] = v.z; d[3] = v.w;
    }
    __syncthreads();

#pragma unroll
    for (int mt = 0; mt < 4; mt++) {
#pragma unroll
        for (int h2 = 0; h2 < 2; h2++) {
            int rl = wr * 64 + mt * 16 + qr + 8 * h2;
            float p = 0.f;
#pragma unroll
            for (int nt = 0; nt < 4; nt++) {
                int j0 = wc * 32 + nt * 8 + 2 * qc;
                p = fmaf(acc[mt][nt][2 * h2],     fs[rl * 132 + j0],     p);
                p = fmaf(acc[mt][nt][2 * h2 + 1], fs[rl * 132 + j0 + 1], p);
            }
            p += __shfl_xor_sync(0xffffffffu, p, 1);
            p += __shfl_xor_sync(0xffffffffu, p, 2);
            if (qc == 0) sRed[rl * 4 + wc] = p;
        }
    }
    __syncthreads();

    if (tid < 128) {
        int row = tid;
        float s = sRed[row * 4 + 0] + sRed[row * 4 + 1]
                + sRed[row * 4 + 2] + sRed[row * 4 + 3];
        // fold b2 bias term: + sum_j b2[nb*128 + j] * feats[row][j]
        const float4* bb2 = (const float4*)(b2 + (size_t)nb * MDIM);
        const float* fr = fs + row * 132;
        float bacc = 0.f;
#pragma unroll
        for (int j = 0; j < 32; j++) {
            float4 v = bb2[j];
            bacc = fmaf(v.x, fr[4 * j + 0],
                   fmaf(v.y, fr[4 * j + 1],
                   fmaf(v.z, fr[4 * j + 2],
                   fmaf(v.w, fr[4 * j + 3], bacc))));
        }
        feats2[(size_t)(m0 + row) * MDIM + nb] =
            __uint_as_float(f2tf32(s + bacc));
    }
}

// =======================================================================
// Host launcher
// =======================================================================
extern "C" void kernel_launch(void* const* d_in, const int* in_sizes, int n_in,
                              void* d_out, int out_size)
{
    const float* x    = (const float*)d_in[0];
    const float* Wmap = (const float*)d_in[1];
    const float* W1   = (const float*)d_in[2];
    const float* b1   = (const float*)d_in[3];
    const float* W2   = (const float*)d_in[4];
    const float* b2   = (const float*)d_in[5];
    float* out = (float*)d_out;

    void *pf, *ph, *pf2, *pwt, *pw2, *pw1, *pwh, *pwl;
    cudaGetSymbolAddress(&pf,  g_feats);
    cudaGetSymbolAddress(&ph,  g_h);
    cudaGetSymbolAddress(&pf2, g_feats2);
    cudaGetSymbolAddress(&pwt, g_wmapT);
    cudaGetSymbolAddress(&pw2, g_w2r);
    cudaGetSymbolAddress(&pw1, g_w1r);
    cudaGetSymbolAddress(&pwh, g_wmh);
    cudaGetSymbolAddress(&pwl, g_wml);
    float* feats  = (float*)pf;
    float* hbuf   = (float*)ph;
    float* feats2 = (float*)pf2;
    float* wmapT  = (float*)pwt;
    float* w2r    = (float*)pw2;
    float* w1r    = (float*)pw1;
    float* wmh    = (float*)pwh;
    float* wml    = (float*)pwl;

    cudaFuncSetAttribute(k3_mma, cudaFuncAttributeMaxDynamicSharedMemorySize,
                         K3_SMEM_BYTES);
    cudaFuncSetAttribute(gemm_3xtf32,
                         cudaFuncAttributeMaxDynamicSharedMemorySize, G3_SMEM);
    cudaFuncSetAttribute(gemm_tf32_k128<EPI_SILU, true>,
                         cudaFuncAttributeMaxDynamicSharedMemorySize, GT_SMEM);
    cudaFuncSetAttribute(gemm_tf32_k128<EPI_RES, false>,
                         cudaFuncAttributeMaxDynamicSharedMemorySize, GT_SMEM);

    dim3 blk(256);

    // 0a) pre-round W2, W1; split W_map into tf32 hi/lo (x split is FUSED)
    round_tf32_kernel<<<2048, blk>>>((const float4*)W2, (float4*)w2r,
                                     MDIM * MDIM * HDIM / 4);
    round_tf32_kernel<<<64, blk>>>((const float4*)W1, (float4*)w1r,
                                   4 * MDIM * MDIM / 4);
    split_tf32_kernel<<<64, blk>>>((const float4*)Wmap, (float4*)wmh,
                                   (float4*)wml, MDIM * VDIM / 4);
    // 0b) WmapT = round(W_map^T)
    transpose_wmap<<<dim3(VDIM / 32, MDIM / 32), blk>>>(Wmap, wmapT);

    // 1) feats = x @ W_map^T  via 3xTF32 with in-register x split
    gemm_3xtf32<<<NROWS / 64, blk, G3_SMEM>>>(x, wmh, wml, feats);

    // 2) h = round(silu(feats @ W1^T + b1))  (tf32, M64 tiles, 2 CTAs/SM)
    gemm_tf32_k128<EPI_SILU, true><<<dim3(NROWS / 64, HDIM / 128), blk, GT_SMEM>>>(
        feats, w1r, b1, nullptr, hbuf, HDIM);

    // 3+4) feats2 = round(((h @ W2r^T) + b2-term) . feats)  — 2 CTAs/SM
    k3_mma<<<dim3(NROWS / K3_BM, MDIM), blk, K3_SMEM_BYTES>>>(
        w2r, feats, hbuf, b2, feats2);

    // 5) out = x + feats2 @ wmapT^T   (tf32, M64 tiles, 2 CTAs/SM)
    gemm_tf32_k128<EPI_RES, false><<<dim3(NROWS / 64, VDIM / 128), blk, GT_SMEM>>>(
        feats2, wmapT, nullptr, x, out, VDIM);
}